// round 14
// baseline (speedup 1.0000x reference)
#include <cuda_runtime.h>

#define DEV_INLINE __device__ __forceinline__

// ---------------- problem constants ----------------
constexpr int Bq = 32;
constexpr int Nq = 512;
constexpr int Tq = 64;
constexpr int Eq = 128;
constexpr int Oq = 64;
constexpr int NSTREAM = 4;
constexpr int BN = Bq * Nq;
constexpr int NWORD = Nq / 32;
constexpr int N_ITERS = 5;
constexpr float LOG2E = 1.4426950408889634f;

// ---------------- device scratch ----------------
__device__ __align__(128) float d_lit[2][BN * Eq];
__device__ __align__(128) float d_emb[NSTREAM][BN * Eq];
__device__ __align__(128) float d_new[NSTREAM][BN * Eq];
__device__ __align__(128) unsigned d_gb[NSTREAM][BN * NWORD];
__device__ __align__(128) float d_h1[NSTREAM][BN];
__device__ __align__(128) float d_h2[NSTREAM][BN];
__device__ __align__(128) float d_xz[2][Bq * Tq * 3 * Eq];
__device__ __align__(128) float d_sem[2][Bq * Eq];
__device__ __align__(128) float d_mid[2][Bq * 2 * Eq];

// ---------------- helpers ----------------
DEV_INLINE float lrelu(float x) { return fmaxf(x, 0.2f * x); }
DEV_INLINE float fsigmoid(float x) { return __fdividef(1.f, 1.f + __expf(-x)); }
DEV_INLINE float ftanh(float x) {
    float e = __expf(2.f * x);
    return 1.f - __fdividef(2.f, e + 1.f);
}
DEV_INLINE float tanh_mufu(float x) {
    float y;
    asm("tanh.approx.f32 %0, %1;" : "=f"(y) : "f"(x));
    return y;
}
DEV_INLINE float fex2(float x) {
    float y;
    asm("ex2.approx.f32 %0, %1;" : "=f"(y) : "f"(x));
    return y;
}

// ---------------- K1: pack 0/1 int graphs into bitmasks ----------------
__global__ void k_pack(const int* __restrict__ c1, const int* __restrict__ l1,
                       const int* __restrict__ c2, const int* __restrict__ l2) {
    int idx = blockIdx.x * blockDim.x + threadIdx.x;
    int w = idx & (NWORD - 1);
    int row = idx >> 4;
    int s = row / BN;
    int bn = row - s * BN;
    const int* src = (s == 0) ? c1 : (s == 1) ? l1 : (s == 2) ? c2 : l2;
    src += (size_t)bn * Nq + w * 32;
    unsigned bits = 0u;
#pragma unroll
    for (int j4 = 0; j4 < 8; j4++) {
        int4 v = ((const int4*)src)[j4];
        bits |= (v.x != 0 ? 1u : 0u) << (4 * j4);
        bits |= (v.y != 0 ? 1u : 0u) << (4 * j4 + 1);
        bits |= (v.z != 0 ? 1u : 0u) << (4 * j4 + 2);
        bits |= (v.w != 0 ? 1u : 0u) << (4 * j4 + 3);
    }
    d_gb[s][bn * NWORD + w] = bits;
}

// ======== scalar register-blocked MAC (setup GEMMs) ========
#define MAC_64x128(Xs, Ws, acc, tx, ty)                                          \
    {                                                                            \
        _Pragma("unroll 4") for (int k = 0; k < Eq; k++) {                       \
            float4 wv = *(const float4*)&(Ws)[k * Eq + (tx) * 4];                \
            float xr[8];                                                         \
            _Pragma("unroll") for (int r = 0; r < 8; r++)                        \
                xr[r] = (Xs)[((ty) * 8 + r) * Eq + k];                           \
            _Pragma("unroll") for (int r = 0; r < 8; r++) {                      \
                acc[r][0] = fmaf(xr[r], wv.x, acc[r][0]);                        \
                acc[r][1] = fmaf(xr[r], wv.y, acc[r][1]);                        \
                acc[r][2] = fmaf(xr[r], wv.z, acc[r][2]);                        \
                acc[r][3] = fmaf(xr[r], wv.w, acc[r][3]);                        \
            }                                                                    \
        }                                                                        \
    }

// ---------------- K2: lit = LITERAL @ W_lit ; emb = relu(lit) ----------------
__global__ void k_lit(const float* __restrict__ lit1, const float* __restrict__ lit2,
                      const float* __restrict__ w1, const float* __restrict__ w2) {
    extern __shared__ float sm[];
    float* Ws = sm;
    float* Xs = sm + Eq * Eq;
    int side = blockIdx.x >> 8;
    int tile = blockIdx.x & 255;
    int tid = threadIdx.x;
    const float* W = side ? w2 : w1;
    const float* X = (side ? lit2 : lit1) + (size_t)tile * 64 * Eq;
    {
        float4* w4 = (float4*)Ws; const float4* g4 = (const float4*)W;
        for (int i = tid; i < Eq * Eq / 4; i += 256) w4[i] = g4[i];
        float4* x4 = (float4*)Xs; const float4* h4 = (const float4*)X;
        for (int i = tid; i < 64 * Eq / 4; i += 256) x4[i] = h4[i];
    }
    __syncthreads();
    int tx = tid & 31, ty = tid >> 5;
    float acc[8][4];
#pragma unroll
    for (int r = 0; r < 8; r++)
#pragma unroll
        for (int c = 0; c < 4; c++) acc[r][c] = 0.f;
    MAC_64x128(Xs, Ws, acc, tx, ty);
#pragma unroll
    for (int r = 0; r < 8; r++) {
        int row = tile * 64 + ty * 8 + r;
        float4 v = make_float4(acc[r][0], acc[r][1], acc[r][2], acc[r][3]);
        *(float4*)&d_lit[side][(size_t)row * Eq + tx * 4] = v;
        float4 rv = make_float4(fmaxf(v.x, 0.f), fmaxf(v.y, 0.f), fmaxf(v.z, 0.f), fmaxf(v.w, 0.f));
        *(float4*)&d_emb[side * 2 + 0][(size_t)row * Eq + tx * 4] = rv;
        *(float4*)&d_emb[side * 2 + 1][(size_t)row * Eq + tx * 4] = rv;
    }
}

// ---------------- K3: XZ = SEMANTIC @ gru_k + b_i  (one gate-chunk/block) -----
__global__ void k_xz(const float* __restrict__ sem1, const float* __restrict__ sem2,
                     const float* __restrict__ k1, const float* __restrict__ k2,
                     const float* __restrict__ gb1, const float* __restrict__ gb2) {
    extern __shared__ float sm[];
    float* Ws = sm;            // [128][128]
    float* Xs = sm + Eq * Eq;  // [64][128]
    int bx = blockIdx.x;       // 192 = 2 sides * 32 tiles * 3 chunks
    int side = bx / 96;
    int r0 = bx - side * 96;
    int tile = r0 / 3;
    int ch = r0 - tile * 3;
    int tid = threadIdx.x;
    const float* K = side ? k2 : k1;
    const float* BI = side ? gb2 : gb1;
    const float* X = (side ? sem2 : sem1) + (size_t)tile * 64 * Eq;
    {
        float4* x4 = (float4*)Xs; const float4* h4 = (const float4*)X;
        for (int i = tid; i < 64 * Eq / 4; i += 256) x4[i] = h4[i];
        for (int i = tid; i < Eq * Eq; i += 256) {
            int kk = i >> 7; int cc = i & 127;
            Ws[i] = K[kk * 384 + ch * 128 + cc];
        }
    }
    __syncthreads();
    int tx = tid & 31, ty = tid >> 5;
    float acc[8][4];
#pragma unroll
    for (int r = 0; r < 8; r++)
#pragma unroll
        for (int c = 0; c < 4; c++) acc[r][c] = 0.f;
    MAC_64x128(Xs, Ws, acc, tx, ty);
    float4 bi = *(const float4*)&BI[ch * 128 + tx * 4];
#pragma unroll
    for (int r = 0; r < 8; r++) {
        int row = tile * 64 + ty * 8 + r;
        float4 v = make_float4(acc[r][0] + bi.x, acc[r][1] + bi.y,
                               acc[r][2] + bi.z, acc[r][3] + bi.w);
        *(float4*)&d_xz[side][(size_t)row * 384 + ch * 128 + tx * 4] = v;
    }
}

// ---------------- K4: GRU recurrence (register-resident rk) ----------------
__global__ __launch_bounds__(384, 1)
void k_gru(const float* __restrict__ rk1, const float* __restrict__ rk2,
           const float* __restrict__ gb1, const float* __restrict__ gb2) {
    __shared__ float hs[128];
    __shared__ float hzs[384];
    int side = blockIdx.x >> 5;
    int b = blockIdx.x & 31;
    int tid = threadIdx.x;
    const float* rk = side ? rk2 : rk1;
    const float* GB = side ? gb2 : gb1;

    float rkr[128];
#pragma unroll
    for (int d = 0; d < 128; d++) rkr[d] = rk[d * 384 + tid];
    float brv = GB[384 + tid];
    if (tid < 128) hs[tid] = 0.f;
    __syncthreads();

    const float* xzb = d_xz[side] + (size_t)(b * Tq) * 384;
    for (int t = 0; t < Tq; t++) {
        float xz0 = 0.f, xz1 = 0.f, xz2 = 0.f;
        if (tid < 128) {
            const float* xzr = xzb + (size_t)t * 384;
            xz0 = xzr[tid];
            xz1 = xzr[128 + tid];
            xz2 = xzr[256 + tid];
        }
        float a0 = brv, a1 = 0.f, a2 = 0.f, a3 = 0.f;
#pragma unroll
        for (int d = 0; d < 128; d += 4) {
            float4 h4 = *(const float4*)&hs[d];
            a0 = fmaf(h4.x, rkr[d], a0);
            a1 = fmaf(h4.y, rkr[d + 1], a1);
            a2 = fmaf(h4.z, rkr[d + 2], a2);
            a3 = fmaf(h4.w, rkr[d + 3], a3);
        }
        hzs[tid] = (a0 + a1) + (a2 + a3);
        __syncthreads();
        if (tid < 128) {
            float z = fsigmoid(xz0 + hzs[tid]);
            float r = fsigmoid(xz1 + hzs[128 + tid]);
            float hh = ftanh(xz2 + r * hzs[256 + tid]);
            hs[tid] = z * hs[tid] + (1.f - z) * hh;
        }
        __syncthreads();
    }
    if (tid < 128) d_sem[side][b * Eq + tid] = hs[tid];
}

// ---------------- K5: attention scores h1,h2 (iteration 0 only) --------------
__global__ void k_scores(const float* __restrict__ cw1, const float* __restrict__ cb1,
                         const float* __restrict__ cw2, const float* __restrict__ cb2,
                         const float* __restrict__ lw1, const float* __restrict__ lb1,
                         const float* __restrict__ lw2, const float* __restrict__ lb2) {
    __shared__ float w1s[Eq], w2s[Eq];
    int s = blockIdx.x >> 6;
    int bn = (blockIdx.x & 63) * 256 + threadIdx.x;
    const float* w1 = (s & 1) ? lw1 : cw1;
    const float* w2 = (s & 1) ? lw2 : cw2;
    float b1 = ((s & 1) ? lb1 : cb1)[0];
    float b2 = ((s & 1) ? lb2 : cb2)[0];
    if (threadIdx.x < Eq) { w1s[threadIdx.x] = w1[threadIdx.x]; w2s[threadIdx.x] = w2[threadIdx.x]; }
    __syncthreads();
    const float4* er = (const float4*)(d_emb[s] + (size_t)bn * Eq);
    float s1 = 0.f, s2 = 0.f;
#pragma unroll
    for (int k = 0; k < 32; k++) {
        float4 v = er[k];
        s1 += v.x * w1s[4 * k] + v.y * w1s[4 * k + 1] + v.z * w1s[4 * k + 2] + v.w * w1s[4 * k + 3];
        s2 += v.x * w2s[4 * k] + v.y * w2s[4 * k + 1] + v.z * w2s[4 * k + 2] + v.w * w2s[4 * k + 3];
    }
    d_h1[s][bn] = s1 + b1;
    d_h2[s][bn] = s2 + b2;
}

// ---------------- cp.async helpers ----------------
DEV_INLINE void cp16(float* dst_smem, const float* src_gmem) {
    unsigned sa = (unsigned)__cvta_generic_to_shared(dst_smem);
    asm volatile("cp.async.cg.shared.global [%0], [%1], 16;" :: "r"(sa), "l"(src_gmem));
}
#define CP_COMMIT() asm volatile("cp.async.commit_group;" ::: "memory")
#define CP_WAIT1() asm volatile("cp.async.wait_group 1;" ::: "memory")
#define CP_WAIT0() asm volatile("cp.async.wait_group 0;" ::: "memory")

// ---------------- K7: attention apply (m32-per-warp, 128 threads) ------------
// 4 warps; warp w owns rows w*32..w*32+31 as TWO m16 tiles sharing B fragments.
// grid 256: covers streams sbase..sbase+1, 128-row i-tile per block.
constexpr int EJS = 136;
__global__ __launch_bounds__(128, 2) void k_av(int sbase) {
    extern __shared__ float sm[];
    float* embJ0 = sm;                          // [64][136]
    float* embJ1 = sm + 64 * EJS;               // [64][136]
    float* h2all = sm + 2 * 64 * EJS;           // [512] (pre-scaled by log2e)
    unsigned* gbs = (unsigned*)(h2all + 512);   // [128][16]

    int bx = blockIdx.x;
    int s = sbase + (bx >> 7);
    int rem = bx & 127;
    int b = rem >> 2;
    int it = rem & 3;
    int i0 = it * 128;
    int tid = threadIdx.x;            // 0..127
    int w = tid >> 5, lane = tid & 31;
    int g = lane >> 2, tg = lane & 3;
    int r0 = w * 32 + g;              // tile A rows: r0, r0+8
    int r2 = w * 32 + 16 + g;         // tile B rows: r2, r2+8

    const float* embR = d_emb[s] + (size_t)(b * Nq) * Eq;

    // prefetch j-tile 0 via cp.async
#pragma unroll
    for (int q = tid; q < 64 * 32; q += 128) {
        int j = q >> 5, c4 = q & 31;
        cp16(&embJ0[j * EJS + c4 * 4], &embR[j * Eq + c4 * 4]);
    }
    CP_COMMIT();

    for (int q = tid; q < 512; q += 128) h2all[q] = LOG2E * d_h2[s][b * Nq + q];
    for (int q = tid; q < 128 * 16; q += 128) {
        int r = q >> 4, wi = q & 15;
        gbs[q] = d_gb[s][(size_t)(b * Nq + i0 + r) * NWORD + wi];
    }
    float h1r0 = LOG2E * d_h1[s][b * Nq + i0 + r0];
    float h1r1 = LOG2E * d_h1[s][b * Nq + i0 + r0 + 8];
    float h1r2 = LOG2E * d_h1[s][b * Nq + i0 + r2];
    float h1r3 = LOG2E * d_h1[s][b * Nq + i0 + r2 + 8];

    float accA[16][4], accB[16][4];
#pragma unroll
    for (int r = 0; r < 16; r++)
#pragma unroll
        for (int c = 0; c < 4; c++) { accA[r][c] = 0.f; accB[r][c] = 0.f; }
    float z0 = 0.f, z1 = 0.f, z2 = 0.f, z3 = 0.f;

    for (int jt = 0; jt < 8; jt++) {
        float* cur = (jt & 1) ? embJ1 : embJ0;
        __syncthreads();
        if (jt < 7) {
            float* nxt = (jt & 1) ? embJ0 : embJ1;
            const float* src = embR + (size_t)((jt + 1) * 64) * Eq;
#pragma unroll
            for (int q = tid; q < 64 * 32; q += 128) {
                int j = q >> 5, c4 = q & 31;
                cp16(&nxt[j * EJS + c4 * 4], &src[j * Eq + c4 * 4]);
            }
            CP_COMMIT();
            CP_WAIT1();
        } else {
            CP_WAIT0();
        }
        __syncthreads();
        unsigned m00 = gbs[r0 * 16 + jt * 2],       m01 = gbs[r0 * 16 + jt * 2 + 1];
        unsigned m10 = gbs[(r0 + 8) * 16 + jt * 2], m11 = gbs[(r0 + 8) * 16 + jt * 2 + 1];
        unsigned m20 = gbs[r2 * 16 + jt * 2],       m21 = gbs[r2 * 16 + jt * 2 + 1];
        unsigned m30 = gbs[(r2 + 8) * 16 + jt * 2], m31 = gbs[(r2 + 8) * 16 + jt * 2 + 1];
        const float* h2t = h2all + jt * 64;
#pragma unroll
        for (int ks = 0; ks < 8; ks++) {
            int k0 = ks * 8;
            int ja = k0 + tg, jb = ja + 4;
            unsigned w0 = (ks < 4) ? m00 : m01;
            unsigned w1m = (ks < 4) ? m10 : m11;
            unsigned w2m = (ks < 4) ? m20 : m21;
            unsigned w3m = (ks < 4) ? m30 : m31;
            float ea = h2t[ja], eb = h2t[jb];
            int ba = ja & 31, bb = jb & 31;
            float a0 = ((w0 >> ba) & 1u) ? fex2(lrelu(h1r0 + ea)) : 0.f;
            float a2 = ((w0 >> bb) & 1u) ? fex2(lrelu(h1r0 + eb)) : 0.f;
            float a1 = ((w1m >> ba) & 1u) ? fex2(lrelu(h1r1 + ea)) : 0.f;
            float a3 = ((w1m >> bb) & 1u) ? fex2(lrelu(h1r1 + eb)) : 0.f;
            float a4 = ((w2m >> ba) & 1u) ? fex2(lrelu(h1r2 + ea)) : 0.f;
            float a6 = ((w2m >> bb) & 1u) ? fex2(lrelu(h1r2 + eb)) : 0.f;
            float a5 = ((w3m >> ba) & 1u) ? fex2(lrelu(h1r3 + ea)) : 0.f;
            float a7 = ((w3m >> bb) & 1u) ? fex2(lrelu(h1r3 + eb)) : 0.f;
            z0 += a0 + a2;
            z1 += a1 + a3;
            z2 += a4 + a6;
            z3 += a5 + a7;
            unsigned ua0 = __float_as_uint(a0), ua1 = __float_as_uint(a1);
            unsigned ua2 = __float_as_uint(a2), ua3 = __float_as_uint(a3);
            unsigned ua4 = __float_as_uint(a4), ua5 = __float_as_uint(a5);
            unsigned ua6 = __float_as_uint(a6), ua7 = __float_as_uint(a7);
#pragma unroll
            for (int nt = 0; nt < 16; nt++) {
                int n = nt * 8;
                unsigned b0 = __float_as_uint(cur[(k0 + tg) * EJS + n + g]);
                unsigned b1 = __float_as_uint(cur[(k0 + tg + 4) * EJS + n + g]);
                asm("mma.sync.aligned.m16n8k8.row.col.f32.tf32.tf32.f32 "
                    "{%0,%1,%2,%3}, {%4,%5,%6,%7}, {%8,%9}, {%0,%1,%2,%3};"
                    : "+f"(accA[nt][0]), "+f"(accA[nt][1]), "+f"(accA[nt][2]), "+f"(accA[nt][3])
                    : "r"(ua0), "r"(ua1), "r"(ua2), "r"(ua3), "r"(b0), "r"(b1));
                asm("mma.sync.aligned.m16n8k8.row.col.f32.tf32.tf32.f32 "
                    "{%0,%1,%2,%3}, {%4,%5,%6,%7}, {%8,%9}, {%0,%1,%2,%3};"
                    : "+f"(accB[nt][0]), "+f"(accB[nt][1]), "+f"(accB[nt][2]), "+f"(accB[nt][3])
                    : "r"(ua4), "r"(ua5), "r"(ua6), "r"(ua7), "r"(b0), "r"(b1));
            }
        }
    }
    // row-sum Z over the tg quad
    z0 += __shfl_xor_sync(0xffffffffu, z0, 1);
    z0 += __shfl_xor_sync(0xffffffffu, z0, 2);
    z1 += __shfl_xor_sync(0xffffffffu, z1, 1);
    z1 += __shfl_xor_sync(0xffffffffu, z1, 2);
    z2 += __shfl_xor_sync(0xffffffffu, z2, 1);
    z2 += __shfl_xor_sync(0xffffffffu, z2, 2);
    z3 += __shfl_xor_sync(0xffffffffu, z3, 1);
    z3 += __shfl_xor_sync(0xffffffffu, z3, 2);
    float sc0 = z0 > 0.f ? __fdividef(1.f, z0) : 0.f;
    float sc1 = z1 > 0.f ? __fdividef(1.f, z1) : 0.f;
    float sc2 = z2 > 0.f ? __fdividef(1.f, z2) : 0.f;
    float sc3 = z3 > 0.f ? __fdividef(1.f, z3) : 0.f;

#pragma unroll
    for (int nt = 0; nt < 16; nt++) {
        int n = nt * 8;
        size_t o0 = (size_t)(b * Nq + i0 + r0) * Eq + n + 2 * tg;
        size_t o1 = (size_t)(b * Nq + i0 + r0 + 8) * Eq + n + 2 * tg;
        size_t o2 = (size_t)(b * Nq + i0 + r2) * Eq + n + 2 * tg;
        size_t o3 = (size_t)(b * Nq + i0 + r2 + 8) * Eq + n + 2 * tg;
        *(float2*)&d_new[s][o0] = make_float2(accA[nt][0] * sc0, accA[nt][1] * sc0);
        *(float2*)&d_new[s][o1] = make_float2(accA[nt][2] * sc1, accA[nt][3] * sc1);
        *(float2*)&d_new[s][o2] = make_float2(accB[nt][0] * sc2, accB[nt][1] * sc2);
        *(float2*)&d_new[s][o3] = make_float2(accB[nt][2] * sc3, accB[nt][3] * sc3);
    }
}

// ---------------- K8: fused MLP + next-iteration scores ----------------
// grid 512: tiles tbase..tbase+511 (256 tiles per stream)
constexpr int XSS = 132;
constexpr int WSS = 136;
__global__ void k_mlp(int tbase,
                      const float* __restrict__ W1, const float* __restrict__ W2,
                      const float* __restrict__ cw1, const float* __restrict__ cb1,
                      const float* __restrict__ cw2, const float* __restrict__ cb2,
                      const float* __restrict__ lw1, const float* __restrict__ lb1,
                      const float* __restrict__ lw2, const float* __restrict__ lb2) {
    extern __shared__ float sm[];
    float* Xs = sm;                   // [64][132]
    float* Ws = sm + 64 * XSS;        // [128][136]
    float* w1s = Ws + 128 * WSS;      // [128]
    float* w2s = w1s + 128;           // [128]
    float* sc1 = w2s + 128;           // [64][2]
    float* sc2 = sc1 + 128;           // [64][2]
    int tile = tbase + blockIdx.x;
    int tid = threadIdx.x;
    int w = tid >> 5, lane = tid & 31;
    int wm = w >> 1, wn = w & 1;
    int mr = wm * 16, cn = wn * 64;
    int g = lane >> 2, tg = lane & 3;

    int s = tile >> 8;
    int lfg = s & 1;
    const float* aw1 = lfg ? lw1 : cw1;
    const float* aw2 = lfg ? lw2 : cw2;
    float ab1 = (lfg ? lb1 : cb1)[0];
    float ab2 = (lfg ? lb2 : cb2)[0];

    const float* X = &d_new[0][0] + (size_t)tile * 64 * Eq;
    for (int q = tid; q < 64 * 32; q += 256) {
        int r = q >> 5, c4 = q & 31;
        cp16(&Xs[r * XSS + c4 * 4], &X[r * Eq + c4 * 4]);
    }
    for (int q = tid; q < 128 * 32; q += 256) {
        int k = q >> 5, c4 = q & 31;
        cp16(&Ws[k * WSS + c4 * 4], &W1[k * Eq + c4 * 4]);
    }
    CP_COMMIT();
    if (tid < 128) { w1s[tid] = aw1[tid]; w2s[tid] = aw2[tid]; }
    CP_WAIT0();
    __syncthreads();

    float acc[8][4];
#pragma unroll
    for (int r = 0; r < 8; r++)
#pragma unroll
        for (int c = 0; c < 4; c++) acc[r][c] = 0.f;
#pragma unroll
    for (int ks = 0; ks < 16; ks++) {
        int k0 = ks * 8;
        unsigned a0 = __float_as_uint(Xs[(mr + g) * XSS + k0 + tg]);
        unsigned a1 = __float_as_uint(Xs[(mr + g + 8) * XSS + k0 + tg]);
        unsigned a2 = __float_as_uint(Xs[(mr + g) * XSS + k0 + tg + 4]);
        unsigned a3 = __float_as_uint(Xs[(mr + g + 8) * XSS + k0 + tg + 4]);
#pragma unroll
        for (int nt = 0; nt < 8; nt++) {
            int n = cn + nt * 8;
            unsigned b0 = __float_as_uint(Ws[(k0 + tg) * WSS + n + g]);
            unsigned b1 = __float_as_uint(Ws[(k0 + tg + 4) * WSS + n + g]);
            asm("mma.sync.aligned.m16n8k8.row.col.f32.tf32.tf32.f32 "
                "{%0,%1,%2,%3}, {%4,%5,%6,%7}, {%8,%9}, {%0,%1,%2,%3};"
                : "+f"(acc[nt][0]), "+f"(acc[nt][1]), "+f"(acc[nt][2]), "+f"(acc[nt][3])
                : "r"(a0), "r"(a1), "r"(a2), "r"(a3), "r"(b0), "r"(b1));
        }
    }
    __syncthreads();

    int side = s >> 1;
    int rbase = tile * 64 - s * BN;

#pragma unroll
    for (int nt = 0; nt < 8; nt++) {
        int n = cn + nt * 8;
        Xs[(mr + g) * XSS + n + 2 * tg]         = fmaxf(acc[nt][0], 0.f);
        Xs[(mr + g) * XSS + n + 2 * tg + 1]     = fmaxf(acc[nt][1], 0.f);
        Xs[(mr + g + 8) * XSS + n + 2 * tg]     = fmaxf(acc[nt][2], 0.f);
        Xs[(mr + g + 8) * XSS + n + 2 * tg + 1] = fmaxf(acc[nt][3], 0.f);
    }
    for (int q = tid; q < 128 * 32; q += 256) {
        int k = q >> 5, c4 = q & 31;
        cp16(&Ws[k * WSS + c4 * 4], &W2[k * Eq + c4 * 4]);
    }
    CP_COMMIT();
    // prefetch lit tile into registers while cp.async + mma run
    float2 lv[8][2];
#pragma unroll
    for (int nt = 0; nt < 8; nt++) {
        int n = cn + nt * 8;
        lv[nt][0] = *(const float2*)&d_lit[side][(size_t)(rbase + mr + g) * Eq + n + 2 * tg];
        lv[nt][1] = *(const float2*)&d_lit[side][(size_t)(rbase + mr + g + 8) * Eq + n + 2 * tg];
    }
    CP_WAIT0();
    __syncthreads();

#pragma unroll
    for (int r = 0; r < 8; r++)
#pragma unroll
        for (int c = 0; c < 4; c++) acc[r][c] = 0.f;
#pragma unroll
    for (int ks = 0; ks < 16; ks++) {
        int k0 = ks * 8;
        unsigned a0 = __float_as_uint(Xs[(mr + g) * XSS + k0 + tg]);
        unsigned a1 = __float_as_uint(Xs[(mr + g + 8) * XSS + k0 + tg]);
        unsigned a2 = __float_as_uint(Xs[(mr + g) * XSS + k0 + tg + 4]);
        unsigned a3 = __float_as_uint(Xs[(mr + g + 8) * XSS + k0 + tg + 4]);
#pragma unroll
        for (int nt = 0; nt < 8; nt++) {
            int n = cn + nt * 8;
            unsigned b0 = __float_as_uint(Ws[(k0 + tg) * WSS + n + g]);
            unsigned b1 = __float_as_uint(Ws[(k0 + tg + 4) * WSS + n + g]);
            asm("mma.sync.aligned.m16n8k8.row.col.f32.tf32.tf32.f32 "
                "{%0,%1,%2,%3}, {%4,%5,%6,%7}, {%8,%9}, {%0,%1,%2,%3};"
                : "+f"(acc[nt][0]), "+f"(acc[nt][1]), "+f"(acc[nt][2]), "+f"(acc[nt][3])
                : "r"(a0), "r"(a1), "r"(a2), "r"(a3), "r"(b0), "r"(b1));
        }
    }

    float p1[2] = {0.f, 0.f}, p2[2] = {0.f, 0.f};
#pragma unroll
    for (int nt = 0; nt < 8; nt++) {
        int n = cn + nt * 8;
#pragma unroll
        for (int hh = 0; hh < 2; hh++) {
            int rloc = mr + g + hh * 8;
            float2 l2v = lv[nt][hh];
            float t0 = tanh_mufu(l2v.x + acc[nt][2 * hh + 0]);
            float t1 = tanh_mufu(l2v.y + acc[nt][2 * hh + 1]);
            size_t o = ((size_t)tile * 64 + rloc) * Eq + n + 2 * tg;
            *(float2*)&(&d_emb[0][0])[o] = make_float2(t0, t1);
            p1[hh] += t0 * w1s[n + 2 * tg] + t1 * w1s[n + 2 * tg + 1];
            p2[hh] += t0 * w2s[n + 2 * tg] + t1 * w2s[n + 2 * tg + 1];
        }
    }
#pragma unroll
    for (int hh = 0; hh < 2; hh++) {
        p1[hh] += __shfl_xor_sync(0xffffffffu, p1[hh], 1);
        p1[hh] += __shfl_xor_sync(0xffffffffu, p1[hh], 2);
        p2[hh] += __shfl_xor_sync(0xffffffffu, p2[hh], 1);
        p2[hh] += __shfl_xor_sync(0xffffffffu, p2[hh], 2);
        if (tg == 0) {
            int rloc = mr + g + hh * 8;
            sc1[rloc * 2 + wn] = p1[hh];
            sc2[rloc * 2 + wn] = p2[hh];
        }
    }
    __syncthreads();
    if (tid < 64) {
        int bn = rbase + tid;
        d_h1[s][bn] = sc1[tid * 2] + sc1[tid * 2 + 1] + ab1;
        d_h2[s][bn] = sc2[tid * 2] + sc2[tid * 2 + 1] + ab2;
    }
}

// ---------------- K10: mid = sum_N concat(cfg_e, lfg_e) — per side -----------
__global__ void k_colsum(int side) {
    int b = blockIdx.x;              // 32 blocks
    int e2 = threadIdx.x;
    int st = side * 2 + (e2 >> 7);
    int e = e2 & 127;
    float sum = 0.f;
    const float* base = d_emb[st] + (size_t)b * Nq * Eq + e;
    for (int i = 0; i < Nq; i++) sum += base[(size_t)i * Eq];
    d_mid[side][b * 256 + e2] = sum;
}

// ---------------- K11: output head + cosine ----------------
__global__ void k_final(const float* __restrict__ Wout, const float* __restrict__ bout,
                        float* __restrict__ out) {
    int b = blockIdx.x;
    int o = threadIdx.x;
    float e[2];
#pragma unroll
    for (int side = 0; side < 2; side++) {
        float a = bout[o];
        const float* mid = d_mid[side] + b * 256;
        for (int k = 0; k < 256; k++) a = fmaf(mid[k], Wout[k * Oq + o], a);
        const float* se = d_sem[side] + b * Eq;
        for (int k = 0; k < 128; k++) a = fmaf(se[k], Wout[(256 + k) * Oq + o], a);
        e[side] = a;
    }
    float p = e[0] * e[1], q0 = e[0] * e[0], q1 = e[1] * e[1];
#pragma unroll
    for (int off = 16; off; off >>= 1) {
        p += __shfl_xor_sync(0xffffffffu, p, off);
        q0 += __shfl_xor_sync(0xffffffffu, q0, off);
        q1 += __shfl_xor_sync(0xffffffffu, q1, off);
    }
    __shared__ float sp[2], s0[2], s1[2];
    if ((o & 31) == 0) { int w = o >> 5; sp[w] = p; s0[w] = q0; s1[w] = q1; }
    __syncthreads();
    if (o == 0) {
        float dot = sp[0] + sp[1];
        float n0 = s0[0] + s0[1];
        float n1 = s1[0] + s1[1];
        out[b] = 0.5f * (1.f + dot * rsqrtf(fmaxf(n0, 1e-12f)) * rsqrtf(fmaxf(n1, 1e-12f)));
    }
}

// ---------------- host launcher ----------------
constexpr int GEMM_SMEM = (Eq * Eq + 64 * Eq) * 4;
constexpr int MLP_SMEM = (64 * XSS + 128 * WSS + 128 + 128 + 128 + 128) * 4;   // 105472
constexpr int AV_SMEM = (2 * 64 * EJS + 512) * 4 + 128 * 16 * 4;               // 79872

extern "C" void kernel_launch(void* const* d_in, const int* in_sizes, int n_in,
                              void* d_out, int out_size) {
    const int* CFG1 = (const int*)d_in[0];
    const int* LFG1 = (const int*)d_in[1];
    const float* LIT1 = (const float*)d_in[2];
    const float* SEM1 = (const float*)d_in[3];
    const int* CFG2 = (const int*)d_in[4];
    const int* LFG2 = (const int*)d_in[5];
    const float* LIT2 = (const float*)d_in[6];
    const float* SEM2 = (const float*)d_in[7];
    const float* Wlit1 = (const float*)d_in[8];
    const float* gk1 = (const float*)d_in[9];
    const float* grk1 = (const float*)d_in[10];
    const float* gb1 = (const float*)d_in[11];
    const float* Wlit2 = (const float*)d_in[12];
    const float* gk2 = (const float*)d_in[13];
    const float* grk2 = (const float*)d_in[14];
    const float* gb2 = (const float*)d_in[15];
    const float* ca1w = (const float*)d_in[16];
    const float* ca1b = (const float*)d_in[17];
    const float* ca2w = (const float*)d_in[18];
    const float* ca2b = (const float*)d_in[19];
    const float* la1w = (const float*)d_in[20];
    const float* la1b = (const float*)d_in[21];
    const float* la2w = (const float*)d_in[22];
    const float* la2b = (const float*)d_in[23];
    const float* mlp1 = (const float*)d_in[24];
    const float* mlp2 = (const float*)d_in[25];
    const float* Wout = (const float*)d_in[26];
    const float* bout = (const float*)d_in[27];
    float* out = (float*)d_out;

    // one-time resources (3 streams — proven to stay inside the memory guard)
    static bool inited = false;
    static cudaStream_t sA, sB, sC;
    static cudaEvent_t evRoot, evP, evB, evA, evC;
    if (!inited) {
        cudaStreamCreateWithFlags(&sA, cudaStreamNonBlocking);
        cudaStreamCreateWithFlags(&sB, cudaStreamNonBlocking);
        cudaStreamCreateWithFlags(&sC, cudaStreamNonBlocking);
        cudaEventCreateWithFlags(&evRoot, cudaEventDisableTiming);
        cudaEventCreateWithFlags(&evP, cudaEventDisableTiming);
        cudaEventCreateWithFlags(&evB, cudaEventDisableTiming);
        cudaEventCreateWithFlags(&evA, cudaEventDisableTiming);
        cudaEventCreateWithFlags(&evC, cudaEventDisableTiming);
        cudaFuncSetAttribute(k_lit, cudaFuncAttributeMaxDynamicSharedMemorySize, GEMM_SMEM);
        cudaFuncSetAttribute(k_xz, cudaFuncAttributeMaxDynamicSharedMemorySize, GEMM_SMEM);
        cudaFuncSetAttribute(k_av, cudaFuncAttributeMaxDynamicSharedMemorySize, AV_SMEM);
        cudaFuncSetAttribute(k_mlp, cudaFuncAttributeMaxDynamicSharedMemorySize, MLP_SMEM);
        inited = true;
    }

    // fork side streams off the capture-origin (legacy) stream
    cudaEventRecord(evRoot, 0);
    cudaStreamWaitEvent(sA, evRoot, 0);
    cudaStreamWaitEvent(sB, evRoot, 0);

    // stream 0: graph bitmask packing (DRAM-bound)
    k_pack<<<4 * BN * NWORD / 256, 256, 0, 0>>>(CFG1, LFG1, CFG2, LFG2);
    cudaEventRecord(evP, 0);

    // stream sB: lit GEMM -> initial scores (compute-bound, overlaps k_pack)
    k_lit<<<512, 256, GEMM_SMEM, sB>>>(LIT1, LIT2, Wlit1, Wlit2);
    k_scores<<<256, 256, 0, sB>>>(ca1w, ca1b, ca2w, ca2b, la1w, la1b, la2w, la2b);
    cudaEventRecord(evB, sB);

    // stream sA: GRU chain — result only needed by k_final
    k_xz<<<192, 256, GEMM_SMEM, sA>>>(SEM1, SEM2, gk1, gk2, gb1, gb2);
    k_gru<<<64, 384, 0, sA>>>(grk1, grk2, gb1, gb2);
    cudaEventRecord(evA, sA);

    // iteration loop: two independent chains (streams 0..1 | streams 2..3)
    cudaStreamWaitEvent(0, evB, 0);
    cudaStreamWaitEvent(sC, evB, 0);
    cudaStreamWaitEvent(sC, evP, 0);
    for (int it = 0; it < N_ITERS; it++) {
        k_av<<<256, 128, AV_SMEM, 0>>>(0);
        k_mlp<<<512, 256, MLP_SMEM, 0>>>(0, mlp1, mlp2,
                                         ca1w, ca1b, ca2w, ca2b,
                                         la1w, la1b, la2w, la2b);
        k_av<<<256, 128, AV_SMEM, sC>>>(2);
        k_mlp<<<512, 256, MLP_SMEM, sC>>>(512, mlp1, mlp2,
                                          ca1w, ca1b, ca2w, ca2b,
                                          la1w, la1b, la2w, la2b);
    }
    // per-side column sums overlap the other chain's tail
    k_colsum<<<32, 256, 0, 0>>>(0);
    k_colsum<<<32, 256, 0, sC>>>(1);
    cudaEventRecord(evC, sC);
    cudaStreamWaitEvent(0, evC, 0);
    cudaStreamWaitEvent(0, evA, 0);
    k_final<<<32, 64, 0, 0>>>(Wout, bout, out);
}

// round 15
// speedup vs baseline: 1.0683x; 1.0683x over previous
#include <cuda_runtime.h>

#define DEV_INLINE __device__ __forceinline__

// ---------------- problem constants ----------------
constexpr int Bq = 32;
constexpr int Nq = 512;
constexpr int Tq = 64;
constexpr int Eq = 128;
constexpr int Oq = 64;
constexpr int NSTREAM = 4;
constexpr int BN = Bq * Nq;
constexpr int NWORD = Nq / 32;
constexpr int N_ITERS = 5;
constexpr float LOG2E = 1.4426950408889634f;

// ---------------- device scratch ----------------
__device__ __align__(128) float d_lit[2][BN * Eq];
__device__ __align__(128) float d_emb[NSTREAM][BN * Eq];
__device__ __align__(128) float d_new[NSTREAM][BN * Eq];
__device__ __align__(128) unsigned d_gb[NSTREAM][BN * NWORD];
__device__ __align__(128) float d_h1[NSTREAM][BN];
__device__ __align__(128) float d_h2[NSTREAM][BN];
__device__ __align__(128) float d_xz[2][Bq * Tq * 3 * Eq];
__device__ __align__(128) float d_sem[2][Bq * Eq];
__device__ __align__(128) float d_mid[2][Bq * 2 * Eq];

// ---------------- helpers ----------------
DEV_INLINE float lrelu(float x) { return fmaxf(x, 0.2f * x); }
DEV_INLINE float fsigmoid(float x) { return __fdividef(1.f, 1.f + __expf(-x)); }
DEV_INLINE float ftanh(float x) {
    float e = __expf(2.f * x);
    return 1.f - __fdividef(2.f, e + 1.f);
}
DEV_INLINE float tanh_mufu(float x) {
    float y;
    asm("tanh.approx.f32 %0, %1;" : "=f"(y) : "f"(x));
    return y;
}
DEV_INLINE float fex2(float x) {
    float y;
    asm("ex2.approx.f32 %0, %1;" : "=f"(y) : "f"(x));
    return y;
}

// ---------------- K1: pack 0/1 int graphs into bitmasks ----------------
__global__ void k_pack(const int* __restrict__ c1, const int* __restrict__ l1,
                       const int* __restrict__ c2, const int* __restrict__ l2) {
    int idx = blockIdx.x * blockDim.x + threadIdx.x;
    int w = idx & (NWORD - 1);
    int row = idx >> 4;
    int s = row / BN;
    int bn = row - s * BN;
    const int* src = (s == 0) ? c1 : (s == 1) ? l1 : (s == 2) ? c2 : l2;
    src += (size_t)bn * Nq + w * 32;
    unsigned bits = 0u;
#pragma unroll
    for (int j4 = 0; j4 < 8; j4++) {
        int4 v = ((const int4*)src)[j4];
        bits |= (v.x != 0 ? 1u : 0u) << (4 * j4);
        bits |= (v.y != 0 ? 1u : 0u) << (4 * j4 + 1);
        bits |= (v.z != 0 ? 1u : 0u) << (4 * j4 + 2);
        bits |= (v.w != 0 ? 1u : 0u) << (4 * j4 + 3);
    }
    d_gb[s][bn * NWORD + w] = bits;
}

// ======== scalar register-blocked MAC (setup GEMMs) ========
#define MAC_64x128(Xs, Ws, acc, tx, ty)                                          \
    {                                                                            \
        _Pragma("unroll 4") for (int k = 0; k < Eq; k++) {                       \
            float4 wv = *(const float4*)&(Ws)[k * Eq + (tx) * 4];                \
            float xr[8];                                                         \
            _Pragma("unroll") for (int r = 0; r < 8; r++)                        \
                xr[r] = (Xs)[((ty) * 8 + r) * Eq + k];                           \
            _Pragma("unroll") for (int r = 0; r < 8; r++) {                      \
                acc[r][0] = fmaf(xr[r], wv.x, acc[r][0]);                        \
                acc[r][1] = fmaf(xr[r], wv.y, acc[r][1]);                        \
                acc[r][2] = fmaf(xr[r], wv.z, acc[r][2]);                        \
                acc[r][3] = fmaf(xr[r], wv.w, acc[r][3]);                        \
            }                                                                    \
        }                                                                        \
    }

// ---------------- K2: lit = LITERAL @ W_lit ; emb = relu(lit) ----------------
__global__ void k_lit(const float* __restrict__ lit1, const float* __restrict__ lit2,
                      const float* __restrict__ w1, const float* __restrict__ w2) {
    extern __shared__ float sm[];
    float* Ws = sm;
    float* Xs = sm + Eq * Eq;
    int side = blockIdx.x >> 8;
    int tile = blockIdx.x & 255;
    int tid = threadIdx.x;
    const float* W = side ? w2 : w1;
    const float* X = (side ? lit2 : lit1) + (size_t)tile * 64 * Eq;
    {
        float4* w4 = (float4*)Ws; const float4* g4 = (const float4*)W;
        for (int i = tid; i < Eq * Eq / 4; i += 256) w4[i] = g4[i];
        float4* x4 = (float4*)Xs; const float4* h4 = (const float4*)X;
        for (int i = tid; i < 64 * Eq / 4; i += 256) x4[i] = h4[i];
    }
    __syncthreads();
    int tx = tid & 31, ty = tid >> 5;
    float acc[8][4];
#pragma unroll
    for (int r = 0; r < 8; r++)
#pragma unroll
        for (int c = 0; c < 4; c++) acc[r][c] = 0.f;
    MAC_64x128(Xs, Ws, acc, tx, ty);
#pragma unroll
    for (int r = 0; r < 8; r++) {
        int row = tile * 64 + ty * 8 + r;
        float4 v = make_float4(acc[r][0], acc[r][1], acc[r][2], acc[r][3]);
        *(float4*)&d_lit[side][(size_t)row * Eq + tx * 4] = v;
        float4 rv = make_float4(fmaxf(v.x, 0.f), fmaxf(v.y, 0.f), fmaxf(v.z, 0.f), fmaxf(v.w, 0.f));
        *(float4*)&d_emb[side * 2 + 0][(size_t)row * Eq + tx * 4] = rv;
        *(float4*)&d_emb[side * 2 + 1][(size_t)row * Eq + tx * 4] = rv;
    }
}

// ---------------- K3: XZ = SEMANTIC @ gru_k + b_i  (one gate-chunk/block) -----
__global__ void k_xz(const float* __restrict__ sem1, const float* __restrict__ sem2,
                     const float* __restrict__ k1, const float* __restrict__ k2,
                     const float* __restrict__ gb1, const float* __restrict__ gb2) {
    extern __shared__ float sm[];
    float* Ws = sm;            // [128][128]
    float* Xs = sm + Eq * Eq;  // [64][128]
    int bx = blockIdx.x;       // 192 = 2 sides * 32 tiles * 3 chunks
    int side = bx / 96;
    int r0 = bx - side * 96;
    int tile = r0 / 3;
    int ch = r0 - tile * 3;
    int tid = threadIdx.x;
    const float* K = side ? k2 : k1;
    const float* BI = side ? gb2 : gb1;
    const float* X = (side ? sem2 : sem1) + (size_t)tile * 64 * Eq;
    {
        float4* x4 = (float4*)Xs; const float4* h4 = (const float4*)X;
        for (int i = tid; i < 64 * Eq / 4; i += 256) x4[i] = h4[i];
        for (int i = tid; i < Eq * Eq; i += 256) {
            int kk = i >> 7; int cc = i & 127;
            Ws[i] = K[kk * 384 + ch * 128 + cc];
        }
    }
    __syncthreads();
    int tx = tid & 31, ty = tid >> 5;
    float acc[8][4];
#pragma unroll
    for (int r = 0; r < 8; r++)
#pragma unroll
        for (int c = 0; c < 4; c++) acc[r][c] = 0.f;
    MAC_64x128(Xs, Ws, acc, tx, ty);
    float4 bi = *(const float4*)&BI[ch * 128 + tx * 4];
#pragma unroll
    for (int r = 0; r < 8; r++) {
        int row = tile * 64 + ty * 8 + r;
        float4 v = make_float4(acc[r][0] + bi.x, acc[r][1] + bi.y,
                               acc[r][2] + bi.z, acc[r][3] + bi.w);
        *(float4*)&d_xz[side][(size_t)row * 384 + ch * 128 + tx * 4] = v;
    }
}

// ---------------- K4: GRU recurrence (register-resident rk) ----------------
__global__ __launch_bounds__(384, 1)
void k_gru(const float* __restrict__ rk1, const float* __restrict__ rk2,
           const float* __restrict__ gb1, const float* __restrict__ gb2) {
    __shared__ float hs[128];
    __shared__ float hzs[384];
    int side = blockIdx.x >> 5;
    int b = blockIdx.x & 31;
    int tid = threadIdx.x;
    const float* rk = side ? rk2 : rk1;
    const float* GB = side ? gb2 : gb1;

    float rkr[128];
#pragma unroll
    for (int d = 0; d < 128; d++) rkr[d] = rk[d * 384 + tid];
    float brv = GB[384 + tid];
    if (tid < 128) hs[tid] = 0.f;
    __syncthreads();

    const float* xzb = d_xz[side] + (size_t)(b * Tq) * 384;
    for (int t = 0; t < Tq; t++) {
        float xz0 = 0.f, xz1 = 0.f, xz2 = 0.f;
        if (tid < 128) {
            const float* xzr = xzb + (size_t)t * 384;
            xz0 = xzr[tid];
            xz1 = xzr[128 + tid];
            xz2 = xzr[256 + tid];
        }
        float a0 = brv, a1 = 0.f, a2 = 0.f, a3 = 0.f;
#pragma unroll
        for (int d = 0; d < 128; d += 4) {
            float4 h4 = *(const float4*)&hs[d];
            a0 = fmaf(h4.x, rkr[d], a0);
            a1 = fmaf(h4.y, rkr[d + 1], a1);
            a2 = fmaf(h4.z, rkr[d + 2], a2);
            a3 = fmaf(h4.w, rkr[d + 3], a3);
        }
        hzs[tid] = (a0 + a1) + (a2 + a3);
        __syncthreads();
        if (tid < 128) {
            float z = fsigmoid(xz0 + hzs[tid]);
            float r = fsigmoid(xz1 + hzs[128 + tid]);
            float hh = ftanh(xz2 + r * hzs[256 + tid]);
            hs[tid] = z * hs[tid] + (1.f - z) * hh;
        }
        __syncthreads();
    }
    if (tid < 128) d_sem[side][b * Eq + tid] = hs[tid];
}

// ---------------- K5: attention scores h1,h2 (iteration 0 only) --------------
__global__ void k_scores(const float* __restrict__ cw1, const float* __restrict__ cb1,
                         const float* __restrict__ cw2, const float* __restrict__ cb2,
                         const float* __restrict__ lw1, const float* __restrict__ lb1,
                         const float* __restrict__ lw2, const float* __restrict__ lb2) {
    __shared__ float w1s[Eq], w2s[Eq];
    int s = blockIdx.x >> 6;
    int bn = (blockIdx.x & 63) * 256 + threadIdx.x;
    const float* w1 = (s & 1) ? lw1 : cw1;
    const float* w2 = (s & 1) ? lw2 : cw2;
    float b1 = ((s & 1) ? lb1 : cb1)[0];
    float b2 = ((s & 1) ? lb2 : cb2)[0];
    if (threadIdx.x < Eq) { w1s[threadIdx.x] = w1[threadIdx.x]; w2s[threadIdx.x] = w2[threadIdx.x]; }
    __syncthreads();
    const float4* er = (const float4*)(d_emb[s] + (size_t)bn * Eq);
    float s1 = 0.f, s2 = 0.f;
#pragma unroll
    for (int k = 0; k < 32; k++) {
        float4 v = er[k];
        s1 += v.x * w1s[4 * k] + v.y * w1s[4 * k + 1] + v.z * w1s[4 * k + 2] + v.w * w1s[4 * k + 3];
        s2 += v.x * w2s[4 * k] + v.y * w2s[4 * k + 1] + v.z * w2s[4 * k + 2] + v.w * w2s[4 * k + 3];
    }
    d_h1[s][bn] = s1 + b1;
    d_h2[s][bn] = s2 + b2;
}

// ---------------- cp.async helpers ----------------
DEV_INLINE void cp16(float* dst_smem, const float* src_gmem) {
    unsigned sa = (unsigned)__cvta_generic_to_shared(dst_smem);
    asm volatile("cp.async.cg.shared.global [%0], [%1], 16;" :: "r"(sa), "l"(src_gmem));
}
#define CP_COMMIT() asm volatile("cp.async.commit_group;" ::: "memory")
#define CP_WAIT1() asm volatile("cp.async.wait_group 1;" ::: "memory")
#define CP_WAIT0() asm volatile("cp.async.wait_group 0;" ::: "memory")

// ---------------- K7: attention apply (256 thr, m16/warp — proven 768µs ver) --
// grid 256: covers streams sbase..sbase+1
constexpr int EJS = 136;
__global__ void k_av(int sbase) {
    extern __shared__ float sm[];
    float* embJ0 = sm;                          // [64][136]
    float* embJ1 = sm + 64 * EJS;               // [64][136]
    float* h2all = sm + 2 * 64 * EJS;           // [512] (pre-scaled by log2e)
    unsigned* gbs = (unsigned*)(h2all + 512);   // [128][16]

    int bx = blockIdx.x;
    int s = sbase + (bx >> 7);
    int rem = bx & 127;
    int b = rem >> 2;
    int it = rem & 3;
    int i0 = it * 128;
    int tid = threadIdx.x;
    int w = tid >> 5, lane = tid & 31;
    int mr = w * 16;
    int g = lane >> 2, tg = lane & 3;
    int row0 = mr + g, row1 = mr + g + 8;

    const float* embR = d_emb[s] + (size_t)(b * Nq) * Eq;

#pragma unroll
    for (int q = tid; q < 64 * 32; q += 256) {
        int j = q >> 5, c4 = q & 31;
        cp16(&embJ0[j * EJS + c4 * 4], &embR[j * Eq + c4 * 4]);
    }
    CP_COMMIT();

    for (int q = tid; q < 512; q += 256) h2all[q] = LOG2E * d_h2[s][b * Nq + q];
    for (int q = tid; q < 128 * 16; q += 256) {
        int r = q >> 4, wi = q & 15;
        gbs[q] = d_gb[s][(size_t)(b * Nq + i0 + r) * NWORD + wi];
    }
    float h1r0 = LOG2E * d_h1[s][b * Nq + i0 + row0];
    float h1r1 = LOG2E * d_h1[s][b * Nq + i0 + row1];

    float acc[16][4];
#pragma unroll
    for (int r = 0; r < 16; r++)
#pragma unroll
        for (int c = 0; c < 4; c++) acc[r][c] = 0.f;
    float z0 = 0.f, z1 = 0.f;

    for (int jt = 0; jt < 8; jt++) {
        float* cur = (jt & 1) ? embJ1 : embJ0;
        __syncthreads();
        if (jt < 7) {
            float* nxt = (jt & 1) ? embJ0 : embJ1;
            const float* src = embR + (size_t)((jt + 1) * 64) * Eq;
#pragma unroll
            for (int q = tid; q < 64 * 32; q += 256) {
                int j = q >> 5, c4 = q & 31;
                cp16(&nxt[j * EJS + c4 * 4], &src[j * Eq + c4 * 4]);
            }
            CP_COMMIT();
            CP_WAIT1();
        } else {
            CP_WAIT0();
        }
        __syncthreads();
        unsigned m00 = gbs[row0 * 16 + jt * 2], m01 = gbs[row0 * 16 + jt * 2 + 1];
        unsigned m10 = gbs[row1 * 16 + jt * 2], m11 = gbs[row1 * 16 + jt * 2 + 1];
        const float* h2t = h2all + jt * 64;
#pragma unroll
        for (int ks = 0; ks < 8; ks++) {
            int k0 = ks * 8;
            int ja = k0 + tg, jb = ja + 4;
            unsigned mw0 = (ks < 4) ? m00 : m01;
            unsigned mw1 = (ks < 4) ? m10 : m11;
            float ea = h2t[ja], eb = h2t[jb];
            int ba = ja & 31, bb = jb & 31;
            float a0 = ((mw0 >> ba) & 1u) ? fex2(lrelu(h1r0 + ea)) : 0.f;
            float a2 = ((mw0 >> bb) & 1u) ? fex2(lrelu(h1r0 + eb)) : 0.f;
            float a1 = ((mw1 >> ba) & 1u) ? fex2(lrelu(h1r1 + ea)) : 0.f;
            float a3 = ((mw1 >> bb) & 1u) ? fex2(lrelu(h1r1 + eb)) : 0.f;
            z0 += a0 + a2;
            z1 += a1 + a3;
            unsigned ua0 = __float_as_uint(a0), ua1 = __float_as_uint(a1);
            unsigned ua2 = __float_as_uint(a2), ua3 = __float_as_uint(a3);
#pragma unroll
            for (int nt = 0; nt < 16; nt++) {
                int n = nt * 8;
                unsigned b0 = __float_as_uint(cur[(k0 + tg) * EJS + n + g]);
                unsigned b1 = __float_as_uint(cur[(k0 + tg + 4) * EJS + n + g]);
                asm("mma.sync.aligned.m16n8k8.row.col.f32.tf32.tf32.f32 "
                    "{%0,%1,%2,%3}, {%4,%5,%6,%7}, {%8,%9}, {%0,%1,%2,%3};"
                    : "+f"(acc[nt][0]), "+f"(acc[nt][1]), "+f"(acc[nt][2]), "+f"(acc[nt][3])
                    : "r"(ua0), "r"(ua1), "r"(ua2), "r"(ua3), "r"(b0), "r"(b1));
            }
        }
    }
    z0 += __shfl_xor_sync(0xffffffffu, z0, 1);
    z0 += __shfl_xor_sync(0xffffffffu, z0, 2);
    z1 += __shfl_xor_sync(0xffffffffu, z1, 1);
    z1 += __shfl_xor_sync(0xffffffffu, z1, 2);
    float sc0 = z0 > 0.f ? __fdividef(1.f, z0) : 0.f;
    float sc1v = z1 > 0.f ? __fdividef(1.f, z1) : 0.f;

#pragma unroll
    for (int nt = 0; nt < 16; nt++) {
        int n = nt * 8;
        size_t r0 = (size_t)(b * Nq + i0 + row0) * Eq + n + 2 * tg;
        size_t r1 = (size_t)(b * Nq + i0 + row1) * Eq + n + 2 * tg;
        *(float2*)&d_new[s][r0] = make_float2(acc[nt][0] * sc0, acc[nt][1] * sc0);
        *(float2*)&d_new[s][r1] = make_float2(acc[nt][2] * sc1v, acc[nt][3] * sc1v);
    }
}

// ---------------- K8: fused MLP + next-iteration scores (lit reg-prefetch) ----
// grid 512: tiles tbase..tbase+511 (256 tiles per stream)
constexpr int XSS = 132;
constexpr int WSS = 136;
__global__ void k_mlp(int tbase,
                      const float* __restrict__ W1, const float* __restrict__ W2,
                      const float* __restrict__ cw1, const float* __restrict__ cb1,
                      const float* __restrict__ cw2, const float* __restrict__ cb2,
                      const float* __restrict__ lw1, const float* __restrict__ lb1,
                      const float* __restrict__ lw2, const float* __restrict__ lb2) {
    extern __shared__ float sm[];
    float* Xs = sm;                   // [64][132]
    float* Ws = sm + 64 * XSS;        // [128][136]
    float* w1s = Ws + 128 * WSS;      // [128]
    float* w2s = w1s + 128;           // [128]
    float* sc1 = w2s + 128;           // [64][2]
    float* sc2 = sc1 + 128;           // [64][2]
    int tile = tbase + blockIdx.x;
    int tid = threadIdx.x;
    int w = tid >> 5, lane = tid & 31;
    int wm = w >> 1, wn = w & 1;
    int mr = wm * 16, cn = wn * 64;
    int g = lane >> 2, tg = lane & 3;

    int s = tile >> 8;
    int lfg = s & 1;
    const float* aw1 = lfg ? lw1 : cw1;
    const float* aw2 = lfg ? lw2 : cw2;
    float ab1 = (lfg ? lb1 : cb1)[0];
    float ab2 = (lfg ? lb2 : cb2)[0];

    const float* X = &d_new[0][0] + (size_t)tile * 64 * Eq;
    for (int q = tid; q < 64 * 32; q += 256) {
        int r = q >> 5, c4 = q & 31;
        cp16(&Xs[r * XSS + c4 * 4], &X[r * Eq + c4 * 4]);
    }
    for (int q = tid; q < 128 * 32; q += 256) {
        int k = q >> 5, c4 = q & 31;
        cp16(&Ws[k * WSS + c4 * 4], &W1[k * Eq + c4 * 4]);
    }
    CP_COMMIT();
    if (tid < 128) { w1s[tid] = aw1[tid]; w2s[tid] = aw2[tid]; }
    CP_WAIT0();
    __syncthreads();

    float acc[8][4];
#pragma unroll
    for (int r = 0; r < 8; r++)
#pragma unroll
        for (int c = 0; c < 4; c++) acc[r][c] = 0.f;
#pragma unroll
    for (int ks = 0; ks < 16; ks++) {
        int k0 = ks * 8;
        unsigned a0 = __float_as_uint(Xs[(mr + g) * XSS + k0 + tg]);
        unsigned a1 = __float_as_uint(Xs[(mr + g + 8) * XSS + k0 + tg]);
        unsigned a2 = __float_as_uint(Xs[(mr + g) * XSS + k0 + tg + 4]);
        unsigned a3 = __float_as_uint(Xs[(mr + g + 8) * XSS + k0 + tg + 4]);
#pragma unroll
        for (int nt = 0; nt < 8; nt++) {
            int n = cn + nt * 8;
            unsigned b0 = __float_as_uint(Ws[(k0 + tg) * WSS + n + g]);
            unsigned b1 = __float_as_uint(Ws[(k0 + tg + 4) * WSS + n + g]);
            asm("mma.sync.aligned.m16n8k8.row.col.f32.tf32.tf32.f32 "
                "{%0,%1,%2,%3}, {%4,%5,%6,%7}, {%8,%9}, {%0,%1,%2,%3};"
                : "+f"(acc[nt][0]), "+f"(acc[nt][1]), "+f"(acc[nt][2]), "+f"(acc[nt][3])
                : "r"(a0), "r"(a1), "r"(a2), "r"(a3), "r"(b0), "r"(b1));
        }
    }
    __syncthreads();

    int side = s >> 1;
    int rbase = tile * 64 - s * BN;

#pragma unroll
    for (int nt = 0; nt < 8; nt++) {
        int n = cn + nt * 8;
        Xs[(mr + g) * XSS + n + 2 * tg]         = fmaxf(acc[nt][0], 0.f);
        Xs[(mr + g) * XSS + n + 2 * tg + 1]     = fmaxf(acc[nt][1], 0.f);
        Xs[(mr + g + 8) * XSS + n + 2 * tg]     = fmaxf(acc[nt][2], 0.f);
        Xs[(mr + g + 8) * XSS + n + 2 * tg + 1] = fmaxf(acc[nt][3], 0.f);
    }
    for (int q = tid; q < 128 * 32; q += 256) {
        int k = q >> 5, c4 = q & 31;
        cp16(&Ws[k * WSS + c4 * 4], &W2[k * Eq + c4 * 4]);
    }
    CP_COMMIT();
    // prefetch lit tile into registers while cp.async + mma run
    float2 lv[8][2];
#pragma unroll
    for (int nt = 0; nt < 8; nt++) {
        int n = cn + nt * 8;
        lv[nt][0] = *(const float2*)&d_lit[side][(size_t)(rbase + mr + g) * Eq + n + 2 * tg];
        lv[nt][1] = *(const float2*)&d_lit[side][(size_t)(rbase + mr + g + 8) * Eq + n + 2 * tg];
    }
    CP_WAIT0();
    __syncthreads();

#pragma unroll
    for (int r = 0; r < 8; r++)
#pragma unroll
        for (int c = 0; c < 4; c++) acc[r][c] = 0.f;
#pragma unroll
    for (int ks = 0; ks < 16; ks++) {
        int k0 = ks * 8;
        unsigned a0 = __float_as_uint(Xs[(mr + g) * XSS + k0 + tg]);
        unsigned a1 = __float_as_uint(Xs[(mr + g + 8) * XSS + k0 + tg]);
        unsigned a2 = __float_as_uint(Xs[(mr + g) * XSS + k0 + tg + 4]);
        unsigned a3 = __float_as_uint(Xs[(mr + g + 8) * XSS + k0 + tg + 4]);
#pragma unroll
        for (int nt = 0; nt < 8; nt++) {
            int n = cn + nt * 8;
            unsigned b0 = __float_as_uint(Ws[(k0 + tg) * WSS + n + g]);
            unsigned b1 = __float_as_uint(Ws[(k0 + tg + 4) * WSS + n + g]);
            asm("mma.sync.aligned.m16n8k8.row.col.f32.tf32.tf32.f32 "
                "{%0,%1,%2,%3}, {%4,%5,%6,%7}, {%8,%9}, {%0,%1,%2,%3};"
                : "+f"(acc[nt][0]), "+f"(acc[nt][1]), "+f"(acc[nt][2]), "+f"(acc[nt][3])
                : "r"(a0), "r"(a1), "r"(a2), "r"(a3), "r"(b0), "r"(b1));
        }
    }

    float p1[2] = {0.f, 0.f}, p2[2] = {0.f, 0.f};
#pragma unroll
    for (int nt = 0; nt < 8; nt++) {
        int n = cn + nt * 8;
#pragma unroll
        for (int hh = 0; hh < 2; hh++) {
            int rloc = mr + g + hh * 8;
            float2 l2v = lv[nt][hh];
            float t0 = tanh_mufu(l2v.x + acc[nt][2 * hh + 0]);
            float t1 = tanh_mufu(l2v.y + acc[nt][2 * hh + 1]);
            size_t o = ((size_t)tile * 64 + rloc) * Eq + n + 2 * tg;
            *(float2*)&(&d_emb[0][0])[o] = make_float2(t0, t1);
            p1[hh] += t0 * w1s[n + 2 * tg] + t1 * w1s[n + 2 * tg + 1];
            p2[hh] += t0 * w2s[n + 2 * tg] + t1 * w2s[n + 2 * tg + 1];
        }
    }
#pragma unroll
    for (int hh = 0; hh < 2; hh++) {
        p1[hh] += __shfl_xor_sync(0xffffffffu, p1[hh], 1);
        p1[hh] += __shfl_xor_sync(0xffffffffu, p1[hh], 2);
        p2[hh] += __shfl_xor_sync(0xffffffffu, p2[hh], 1);
        p2[hh] += __shfl_xor_sync(0xffffffffu, p2[hh], 2);
        if (tg == 0) {
            int rloc = mr + g + hh * 8;
            sc1[rloc * 2 + wn] = p1[hh];
            sc2[rloc * 2 + wn] = p2[hh];
        }
    }
    __syncthreads();
    if (tid < 64) {
        int bn = rbase + tid;
        d_h1[s][bn] = sc1[tid * 2] + sc1[tid * 2 + 1] + ab1;
        d_h2[s][bn] = sc2[tid * 2] + sc2[tid * 2 + 1] + ab2;
    }
}

// ---------------- K10: mid = sum_N concat(cfg_e, lfg_e) — per side -----------
__global__ void k_colsum(int side) {
    int b = blockIdx.x;
    int e2 = threadIdx.x;
    int st = side * 2 + (e2 >> 7);
    int e = e2 & 127;
    float sum = 0.f;
    const float* base = d_emb[st] + (size_t)b * Nq * Eq + e;
    for (int i = 0; i < Nq; i++) sum += base[(size_t)i * Eq];
    d_mid[side][b * 256 + e2] = sum;
}

// ---------------- K11: output head + cosine ----------------
__global__ void k_final(const float* __restrict__ Wout, const float* __restrict__ bout,
                        float* __restrict__ out) {
    int b = blockIdx.x;
    int o = threadIdx.x;
    float e[2];
#pragma unroll
    for (int side = 0; side < 2; side++) {
        float a = bout[o];
        const float* mid = d_mid[side] + b * 256;
        for (int k = 0; k < 256; k++) a = fmaf(mid[k], Wout[k * Oq + o], a);
        const float* se = d_sem[side] + b * Eq;
        for (int k = 0; k < 128; k++) a = fmaf(se[k], Wout[(256 + k) * Oq + o], a);
        e[side] = a;
    }
    float p = e[0] * e[1], q0 = e[0] * e[0], q1 = e[1] * e[1];
#pragma unroll
    for (int off = 16; off; off >>= 1) {
        p += __shfl_xor_sync(0xffffffffu, p, off);
        q0 += __shfl_xor_sync(0xffffffffu, q0, off);
        q1 += __shfl_xor_sync(0xffffffffu, q1, off);
    }
    __shared__ float sp[2], s0[2], s1[2];
    if ((o & 31) == 0) { int w = o >> 5; sp[w] = p; s0[w] = q0; s1[w] = q1; }
    __syncthreads();
    if (o == 0) {
        float dot = sp[0] + sp[1];
        float n0 = s0[0] + s0[1];
        float n1 = s1[0] + s1[1];
        out[b] = 0.5f * (1.f + dot * rsqrtf(fmaxf(n0, 1e-12f)) * rsqrtf(fmaxf(n1, 1e-12f)));
    }
}

// ---------------- host launcher ----------------
constexpr int GEMM_SMEM = (Eq * Eq + 64 * Eq) * 4;
constexpr int MLP_SMEM = (64 * XSS + 128 * WSS + 128 + 128 + 128 + 128) * 4;   // 105472
constexpr int AV_SMEM = (2 * 64 * EJS + 512) * 4 + 128 * 16 * 4;               // 79872

extern "C" void kernel_launch(void* const* d_in, const int* in_sizes, int n_in,
                              void* d_out, int out_size) {
    const int* CFG1 = (const int*)d_in[0];
    const int* LFG1 = (const int*)d_in[1];
    const float* LIT1 = (const float*)d_in[2];
    const float* SEM1 = (const float*)d_in[3];
    const int* CFG2 = (const int*)d_in[4];
    const int* LFG2 = (const int*)d_in[5];
    const float* LIT2 = (const float*)d_in[6];
    const float* SEM2 = (const float*)d_in[7];
    const float* Wlit1 = (const float*)d_in[8];
    const float* gk1 = (const float*)d_in[9];
    const float* grk1 = (const float*)d_in[10];
    const float* gb1 = (const float*)d_in[11];
    const float* Wlit2 = (const float*)d_in[12];
    const float* gk2 = (const float*)d_in[13];
    const float* grk2 = (const float*)d_in[14];
    const float* gb2 = (const float*)d_in[15];
    const float* ca1w = (const float*)d_in[16];
    const float* ca1b = (const float*)d_in[17];
    const float* ca2w = (const float*)d_in[18];
    const float* ca2b = (const float*)d_in[19];
    const float* la1w = (const float*)d_in[20];
    const float* la1b = (const float*)d_in[21];
    const float* la2w = (const float*)d_in[22];
    const float* la2b = (const float*)d_in[23];
    const float* mlp1 = (const float*)d_in[24];
    const float* mlp2 = (const float*)d_in[25];
    const float* Wout = (const float*)d_in[26];
    const float* bout = (const float*)d_in[27];
    float* out = (float*)d_out;

    // one-time resources (3 streams — proven to stay inside the memory guard)
    static bool inited = false;
    static cudaStream_t sA, sB, sC;
    static cudaEvent_t evRoot, evP, evB, evA, evC;
    if (!inited) {
        cudaStreamCreateWithFlags(&sA, cudaStreamNonBlocking);
        cudaStreamCreateWithFlags(&sB, cudaStreamNonBlocking);
        cudaStreamCreateWithFlags(&sC, cudaStreamNonBlocking);
        cudaEventCreateWithFlags(&evRoot, cudaEventDisableTiming);
        cudaEventCreateWithFlags(&evP, cudaEventDisableTiming);
        cudaEventCreateWithFlags(&evB, cudaEventDisableTiming);
        cudaEventCreateWithFlags(&evA, cudaEventDisableTiming);
        cudaEventCreateWithFlags(&evC, cudaEventDisableTiming);
        cudaFuncSetAttribute(k_lit, cudaFuncAttributeMaxDynamicSharedMemorySize, GEMM_SMEM);
        cudaFuncSetAttribute(k_xz, cudaFuncAttributeMaxDynamicSharedMemorySize, GEMM_SMEM);
        cudaFuncSetAttribute(k_av, cudaFuncAttributeMaxDynamicSharedMemorySize, AV_SMEM);
        cudaFuncSetAttribute(k_mlp, cudaFuncAttributeMaxDynamicSharedMemorySize, MLP_SMEM);
        inited = true;
    }

    // fork side streams off the capture-origin (legacy) stream
    cudaEventRecord(evRoot, 0);
    cudaStreamWaitEvent(sA, evRoot, 0);
    cudaStreamWaitEvent(sB, evRoot, 0);

    // stream 0: graph bitmask packing (DRAM-bound)
    k_pack<<<4 * BN * NWORD / 256, 256, 0, 0>>>(CFG1, LFG1, CFG2, LFG2);
    cudaEventRecord(evP, 0);

    // stream sB: lit GEMM -> initial scores (compute-bound, overlaps k_pack)
    k_lit<<<512, 256, GEMM_SMEM, sB>>>(LIT1, LIT2, Wlit1, Wlit2);
    k_scores<<<256, 256, 0, sB>>>(ca1w, ca1b, ca2w, ca2b, la1w, la1b, la2w, la2b);
    cudaEventRecord(evB, sB);

    // stream sA: GRU chain — result only needed by k_final
    k_xz<<<192, 256, GEMM_SMEM, sA>>>(SEM1, SEM2, gk1, gk2, gb1, gb2);
    k_gru<<<64, 384, 0, sA>>>(grk1, grk2, gb1, gb2);
    cudaEventRecord(evA, sA);

    // iteration loop: two independent chains (streams 0..1 | streams 2..3)
    cudaStreamWaitEvent(0, evB, 0);
    cudaStreamWaitEvent(sC, evB, 0);
    cudaStreamWaitEvent(sC, evP, 0);
    for (int it = 0; it < N_ITERS; it++) {
        k_av<<<256, 256, AV_SMEM, 0>>>(0);
        k_mlp<<<512, 256, MLP_SMEM, 0>>>(0, mlp1, mlp2,
                                         ca1w, ca1b, ca2w, ca2b,
                                         la1w, la1b, la2w, la2b);
        k_av<<<256, 256, AV_SMEM, sC>>>(2);
        k_mlp<<<512, 256, MLP_SMEM, sC>>>(512, mlp1, mlp2,
                                          ca1w, ca1b, ca2w, ca2b,
                                          la1w, la1b, la2w, la2b);
    }
    // per-side column sums overlap the other chain's tail
    k_colsum<<<32, 256, 0, 0>>>(0);
    k_colsum<<<32, 256, 0, sC>>>(1);
    cudaEventRecord(evC, sC);
    cudaStreamWaitEvent(0, evC, 0);
    cudaStreamWaitEvent(0, evA, 0);
    k_final<<<32, 64, 0, 0>>>(Wout, bout, out);
}

// round 16
// speedup vs baseline: 1.1121x; 1.0410x over previous
#include <cuda_runtime.h>

#define DEV_INLINE __device__ __forceinline__

// ---------------- problem constants ----------------
constexpr int Bq = 32;
constexpr int Nq = 512;
constexpr int Tq = 64;
constexpr int Eq = 128;
constexpr int Oq = 64;
constexpr int NSTREAM = 4;
constexpr int BN = Bq * Nq;
constexpr int NWORD = Nq / 32;
constexpr int N_ITERS = 5;
constexpr float LOG2E = 1.4426950408889634f;

// ---------------- device scratch ----------------
__device__ __align__(128) float d_lit[2][BN * Eq];
__device__ __align__(128) float d_emb[NSTREAM][BN * Eq];
__device__ __align__(128) float d_new[NSTREAM][BN * Eq];
__device__ __align__(128) unsigned d_gb[NSTREAM][BN * NWORD];
__device__ __align__(128) float d_h1[NSTREAM][BN];
__device__ __align__(128) float d_h2[NSTREAM][BN];
__device__ __align__(128) float d_xz[2][Bq * Tq * 3 * Eq];
__device__ __align__(128) float d_sem[2][Bq * Eq];
__device__ __align__(128) float d_mid[2][Bq * 2 * Eq];

// ---------------- helpers ----------------
DEV_INLINE float lrelu(float x) { return fmaxf(x, 0.2f * x); }
DEV_INLINE float fsigmoid(float x) { return __fdividef(1.f, 1.f + __expf(-x)); }
DEV_INLINE float ftanh(float x) {
    float e = __expf(2.f * x);
    return 1.f - __fdividef(2.f, e + 1.f);
}
DEV_INLINE float tanh_mufu(float x) {
    float y;
    asm("tanh.approx.f32 %0, %1;" : "=f"(y) : "f"(x));
    return y;
}
DEV_INLINE float fex2(float x) {
    float y;
    asm("ex2.approx.f32 %0, %1;" : "=f"(y) : "f"(x));
    return y;
}

// ---------------- K1: pack bitmasks + zero d_mid ----------------
__global__ void k_pack(const int* __restrict__ c1, const int* __restrict__ l1,
                       const int* __restrict__ c2, const int* __restrict__ l2) {
    int idx = blockIdx.x * blockDim.x + threadIdx.x;
    if (idx < 2 * Bq * 2 * Eq) (&d_mid[0][0])[idx] = 0.f;   // 16384 floats
    int w = idx & (NWORD - 1);
    int row = idx >> 4;
    int s = row / BN;
    int bn = row - s * BN;
    const int* src = (s == 0) ? c1 : (s == 1) ? l1 : (s == 2) ? c2 : l2;
    src += (size_t)bn * Nq + w * 32;
    unsigned bits = 0u;
#pragma unroll
    for (int j4 = 0; j4 < 8; j4++) {
        int4 v = ((const int4*)src)[j4];
        bits |= (v.x != 0 ? 1u : 0u) << (4 * j4);
        bits |= (v.y != 0 ? 1u : 0u) << (4 * j4 + 1);
        bits |= (v.z != 0 ? 1u : 0u) << (4 * j4 + 2);
        bits |= (v.w != 0 ? 1u : 0u) << (4 * j4 + 3);
    }
    d_gb[s][bn * NWORD + w] = bits;
}

// ======== scalar register-blocked MAC (setup GEMMs) ========
#define MAC_64x128(Xs, Ws, acc, tx, ty)                                          \
    {                                                                            \
        _Pragma("unroll 4") for (int k = 0; k < Eq; k++) {                       \
            float4 wv = *(const float4*)&(Ws)[k * Eq + (tx) * 4];                \
            float xr[8];                                                         \
            _Pragma("unroll") for (int r = 0; r < 8; r++)                        \
                xr[r] = (Xs)[((ty) * 8 + r) * Eq + k];                           \
            _Pragma("unroll") for (int r = 0; r < 8; r++) {                      \
                acc[r][0] = fmaf(xr[r], wv.x, acc[r][0]);                        \
                acc[r][1] = fmaf(xr[r], wv.y, acc[r][1]);                        \
                acc[r][2] = fmaf(xr[r], wv.z, acc[r][2]);                        \
                acc[r][3] = fmaf(xr[r], wv.w, acc[r][3]);                        \
            }                                                                    \
        }                                                                        \
    }

// ---------------- K2: lit = LITERAL @ W_lit ; emb = relu(lit) ----------------
__global__ void k_lit(const float* __restrict__ lit1, const float* __restrict__ lit2,
                      const float* __restrict__ w1, const float* __restrict__ w2) {
    extern __shared__ float sm[];
    float* Ws = sm;
    float* Xs = sm + Eq * Eq;
    int side = blockIdx.x >> 8;
    int tile = blockIdx.x & 255;
    int tid = threadIdx.x;
    const float* W = side ? w2 : w1;
    const float* X = (side ? lit2 : lit1) + (size_t)tile * 64 * Eq;
    {
        float4* w4 = (float4*)Ws; const float4* g4 = (const float4*)W;
        for (int i = tid; i < Eq * Eq / 4; i += 256) w4[i] = g4[i];
        float4* x4 = (float4*)Xs; const float4* h4 = (const float4*)X;
        for (int i = tid; i < 64 * Eq / 4; i += 256) x4[i] = h4[i];
    }
    __syncthreads();
    int tx = tid & 31, ty = tid >> 5;
    float acc[8][4];
#pragma unroll
    for (int r = 0; r < 8; r++)
#pragma unroll
        for (int c = 0; c < 4; c++) acc[r][c] = 0.f;
    MAC_64x128(Xs, Ws, acc, tx, ty);
#pragma unroll
    for (int r = 0; r < 8; r++) {
        int row = tile * 64 + ty * 8 + r;
        float4 v = make_float4(acc[r][0], acc[r][1], acc[r][2], acc[r][3]);
        *(float4*)&d_lit[side][(size_t)row * Eq + tx * 4] = v;
        float4 rv = make_float4(fmaxf(v.x, 0.f), fmaxf(v.y, 0.f), fmaxf(v.z, 0.f), fmaxf(v.w, 0.f));
        *(float4*)&d_emb[side * 2 + 0][(size_t)row * Eq + tx * 4] = rv;
        *(float4*)&d_emb[side * 2 + 1][(size_t)row * Eq + tx * 4] = rv;
    }
}

// ---------------- K3: XZ = SEMANTIC @ gru_k + b_i  (one gate-chunk/block) -----
__global__ void k_xz(const float* __restrict__ sem1, const float* __restrict__ sem2,
                     const float* __restrict__ k1, const float* __restrict__ k2,
                     const float* __restrict__ gb1, const float* __restrict__ gb2) {
    extern __shared__ float sm[];
    float* Ws = sm;            // [128][128]
    float* Xs = sm + Eq * Eq;  // [64][128]
    int bx = blockIdx.x;       // 192 = 2 sides * 32 tiles * 3 chunks
    int side = bx / 96;
    int r0 = bx - side * 96;
    int tile = r0 / 3;
    int ch = r0 - tile * 3;
    int tid = threadIdx.x;
    const float* K = side ? k2 : k1;
    const float* BI = side ? gb2 : gb1;
    const float* X = (side ? sem2 : sem1) + (size_t)tile * 64 * Eq;
    {
        float4* x4 = (float4*)Xs; const float4* h4 = (const float4*)X;
        for (int i = tid; i < 64 * Eq / 4; i += 256) x4[i] = h4[i];
        for (int i = tid; i < Eq * Eq; i += 256) {
            int kk = i >> 7; int cc = i & 127;
            Ws[i] = K[kk * 384 + ch * 128 + cc];
        }
    }
    __syncthreads();
    int tx = tid & 31, ty = tid >> 5;
    float acc[8][4];
#pragma unroll
    for (int r = 0; r < 8; r++)
#pragma unroll
        for (int c = 0; c < 4; c++) acc[r][c] = 0.f;
    MAC_64x128(Xs, Ws, acc, tx, ty);
    float4 bi = *(const float4*)&BI[ch * 128 + tx * 4];
#pragma unroll
    for (int r = 0; r < 8; r++) {
        int row = tile * 64 + ty * 8 + r;
        float4 v = make_float4(acc[r][0] + bi.x, acc[r][1] + bi.y,
                               acc[r][2] + bi.z, acc[r][3] + bi.w);
        *(float4*)&d_xz[side][(size_t)row * 384 + ch * 128 + tx * 4] = v;
    }
}

// ---------------- K4: GRU recurrence (register-resident rk) ----------------
__global__ __launch_bounds__(384, 1)
void k_gru(const float* __restrict__ rk1, const float* __restrict__ rk2,
           const float* __restrict__ gb1, const float* __restrict__ gb2) {
    __shared__ float hs[128];
    __shared__ float hzs[384];
    int side = blockIdx.x >> 5;
    int b = blockIdx.x & 31;
    int tid = threadIdx.x;
    const float* rk = side ? rk2 : rk1;
    const float* GB = side ? gb2 : gb1;

    float rkr[128];
#pragma unroll
    for (int d = 0; d < 128; d++) rkr[d] = rk[d * 384 + tid];
    float brv = GB[384 + tid];
    if (tid < 128) hs[tid] = 0.f;
    __syncthreads();

    const float* xzb = d_xz[side] + (size_t)(b * Tq) * 384;
    for (int t = 0; t < Tq; t++) {
        float xz0 = 0.f, xz1 = 0.f, xz2 = 0.f;
        if (tid < 128) {
            const float* xzr = xzb + (size_t)t * 384;
            xz0 = xzr[tid];
            xz1 = xzr[128 + tid];
            xz2 = xzr[256 + tid];
        }
        float a0 = brv, a1 = 0.f, a2 = 0.f, a3 = 0.f;
#pragma unroll
        for (int d = 0; d < 128; d += 4) {
            float4 h4 = *(const float4*)&hs[d];
            a0 = fmaf(h4.x, rkr[d], a0);
            a1 = fmaf(h4.y, rkr[d + 1], a1);
            a2 = fmaf(h4.z, rkr[d + 2], a2);
            a3 = fmaf(h4.w, rkr[d + 3], a3);
        }
        hzs[tid] = (a0 + a1) + (a2 + a3);
        __syncthreads();
        if (tid < 128) {
            float z = fsigmoid(xz0 + hzs[tid]);
            float r = fsigmoid(xz1 + hzs[128 + tid]);
            float hh = ftanh(xz2 + r * hzs[256 + tid]);
            hs[tid] = z * hs[tid] + (1.f - z) * hh;
        }
        __syncthreads();
    }
    if (tid < 128) d_sem[side][b * Eq + tid] = hs[tid];
}

// ---------------- K5: attention scores h1,h2 (iteration 0 only) --------------
__global__ void k_scores(const float* __restrict__ cw1, const float* __restrict__ cb1,
                         const float* __restrict__ cw2, const float* __restrict__ cb2,
                         const float* __restrict__ lw1, const float* __restrict__ lb1,
                         const float* __restrict__ lw2, const float* __restrict__ lb2) {
    __shared__ float w1s[Eq], w2s[Eq];
    int s = blockIdx.x >> 6;
    int bn = (blockIdx.x & 63) * 256 + threadIdx.x;
    const float* w1 = (s & 1) ? lw1 : cw1;
    const float* w2 = (s & 1) ? lw2 : cw2;
    float b1 = ((s & 1) ? lb1 : cb1)[0];
    float b2 = ((s & 1) ? lb2 : cb2)[0];
    if (threadIdx.x < Eq) { w1s[threadIdx.x] = w1[threadIdx.x]; w2s[threadIdx.x] = w2[threadIdx.x]; }
    __syncthreads();
    const float4* er = (const float4*)(d_emb[s] + (size_t)bn * Eq);
    float s1 = 0.f, s2 = 0.f;
#pragma unroll
    for (int k = 0; k < 32; k++) {
        float4 v = er[k];
        s1 += v.x * w1s[4 * k] + v.y * w1s[4 * k + 1] + v.z * w1s[4 * k + 2] + v.w * w1s[4 * k + 3];
        s2 += v.x * w2s[4 * k] + v.y * w2s[4 * k + 1] + v.z * w2s[4 * k + 2] + v.w * w2s[4 * k + 3];
    }
    d_h1[s][bn] = s1 + b1;
    d_h2[s][bn] = s2 + b2;
}

// ---------------- cp.async helpers ----------------
DEV_INLINE void cp16(float* dst_smem, const float* src_gmem) {
    unsigned sa = (unsigned)__cvta_generic_to_shared(dst_smem);
    asm volatile("cp.async.cg.shared.global [%0], [%1], 16;" :: "r"(sa), "l"(src_gmem));
}
#define CP_COMMIT() asm volatile("cp.async.commit_group;" ::: "memory")
#define CP_WAIT1() asm volatile("cp.async.wait_group 1;" ::: "memory")
#define CP_WAIT0() asm volatile("cp.async.wait_group 0;" ::: "memory")

// ---------------- K7: attention apply (256 thr, m16/warp — proven 768µs) -----
// grid 256: covers streams sbase..sbase+1
constexpr int EJS = 136;
__global__ void k_av(int sbase) {
    extern __shared__ float sm[];
    float* embJ0 = sm;                          // [64][136]
    float* embJ1 = sm + 64 * EJS;               // [64][136]
    float* h2all = sm + 2 * 64 * EJS;           // [512] (pre-scaled by log2e)
    unsigned* gbs = (unsigned*)(h2all + 512);   // [128][16]

    int bx = blockIdx.x;
    int s = sbase + (bx >> 7);
    int rem = bx & 127;
    int b = rem >> 2;
    int it = rem & 3;
    int i0 = it * 128;
    int tid = threadIdx.x;
    int w = tid >> 5, lane = tid & 31;
    int mr = w * 16;
    int g = lane >> 2, tg = lane & 3;
    int row0 = mr + g, row1 = mr + g + 8;

    const float* embR = d_emb[s] + (size_t)(b * Nq) * Eq;

#pragma unroll
    for (int q = tid; q < 64 * 32; q += 256) {
        int j = q >> 5, c4 = q & 31;
        cp16(&embJ0[j * EJS + c4 * 4], &embR[j * Eq + c4 * 4]);
    }
    CP_COMMIT();

    for (int q = tid; q < 512; q += 256) h2all[q] = LOG2E * d_h2[s][b * Nq + q];
    for (int q = tid; q < 128 * 16; q += 256) {
        int r = q >> 4, wi = q & 15;
        gbs[q] = d_gb[s][(size_t)(b * Nq + i0 + r) * NWORD + wi];
    }
    float h1r0 = LOG2E * d_h1[s][b * Nq + i0 + row0];
    float h1r1 = LOG2E * d_h1[s][b * Nq + i0 + row1];

    float acc[16][4];
#pragma unroll
    for (int r = 0; r < 16; r++)
#pragma unroll
        for (int c = 0; c < 4; c++) acc[r][c] = 0.f;
    float z0 = 0.f, z1 = 0.f;

    for (int jt = 0; jt < 8; jt++) {
        float* cur = (jt & 1) ? embJ1 : embJ0;
        __syncthreads();
        if (jt < 7) {
            float* nxt = (jt & 1) ? embJ0 : embJ1;
            const float* src = embR + (size_t)((jt + 1) * 64) * Eq;
#pragma unroll
            for (int q = tid; q < 64 * 32; q += 256) {
                int j = q >> 5, c4 = q & 31;
                cp16(&nxt[j * EJS + c4 * 4], &src[j * Eq + c4 * 4]);
            }
            CP_COMMIT();
            CP_WAIT1();
        } else {
            CP_WAIT0();
        }
        __syncthreads();
        unsigned m00 = gbs[row0 * 16 + jt * 2], m01 = gbs[row0 * 16 + jt * 2 + 1];
        unsigned m10 = gbs[row1 * 16 + jt * 2], m11 = gbs[row1 * 16 + jt * 2 + 1];
        const float* h2t = h2all + jt * 64;
#pragma unroll
        for (int ks = 0; ks < 8; ks++) {
            int k0 = ks * 8;
            int ja = k0 + tg, jb = ja + 4;
            unsigned mw0 = (ks < 4) ? m00 : m01;
            unsigned mw1 = (ks < 4) ? m10 : m11;
            float ea = h2t[ja], eb = h2t[jb];
            int ba = ja & 31, bb = jb & 31;
            float a0 = ((mw0 >> ba) & 1u) ? fex2(lrelu(h1r0 + ea)) : 0.f;
            float a2 = ((mw0 >> bb) & 1u) ? fex2(lrelu(h1r0 + eb)) : 0.f;
            float a1 = ((mw1 >> ba) & 1u) ? fex2(lrelu(h1r1 + ea)) : 0.f;
            float a3 = ((mw1 >> bb) & 1u) ? fex2(lrelu(h1r1 + eb)) : 0.f;
            z0 += a0 + a2;
            z1 += a1 + a3;
            unsigned ua0 = __float_as_uint(a0), ua1 = __float_as_uint(a1);
            unsigned ua2 = __float_as_uint(a2), ua3 = __float_as_uint(a3);
#pragma unroll
            for (int nt = 0; nt < 16; nt++) {
                int n = nt * 8;
                unsigned b0 = __float_as_uint(cur[(k0 + tg) * EJS + n + g]);
                unsigned b1 = __float_as_uint(cur[(k0 + tg + 4) * EJS + n + g]);
                asm("mma.sync.aligned.m16n8k8.row.col.f32.tf32.tf32.f32 "
                    "{%0,%1,%2,%3}, {%4,%5,%6,%7}, {%8,%9}, {%0,%1,%2,%3};"
                    : "+f"(acc[nt][0]), "+f"(acc[nt][1]), "+f"(acc[nt][2]), "+f"(acc[nt][3])
                    : "r"(ua0), "r"(ua1), "r"(ua2), "r"(ua3), "r"(b0), "r"(b1));
            }
        }
    }
    z0 += __shfl_xor_sync(0xffffffffu, z0, 1);
    z0 += __shfl_xor_sync(0xffffffffu, z0, 2);
    z1 += __shfl_xor_sync(0xffffffffu, z1, 1);
    z1 += __shfl_xor_sync(0xffffffffu, z1, 2);
    float sc0 = z0 > 0.f ? __fdividef(1.f, z0) : 0.f;
    float sc1v = z1 > 0.f ? __fdividef(1.f, z1) : 0.f;

#pragma unroll
    for (int nt = 0; nt < 16; nt++) {
        int n = nt * 8;
        size_t r0 = (size_t)(b * Nq + i0 + row0) * Eq + n + 2 * tg;
        size_t r1 = (size_t)(b * Nq + i0 + row1) * Eq + n + 2 * tg;
        *(float2*)&d_new[s][r0] = make_float2(acc[nt][0] * sc0, acc[nt][1] * sc0);
        *(float2*)&d_new[s][r1] = make_float2(acc[nt][2] * sc1v, acc[nt][3] * sc1v);
    }
}

// ---------------- K8: fused MLP (+ scores OR final column-sums) ---------------
// grid 512: tiles tbase..tbase+511 (256 tiles per stream)
constexpr int XSS = 132;
constexpr int WSS = 136;
__global__ void k_mlp(int tbase, int last,
                      const float* __restrict__ W1, const float* __restrict__ W2,
                      const float* __restrict__ cw1, const float* __restrict__ cb1,
                      const float* __restrict__ cw2, const float* __restrict__ cb2,
                      const float* __restrict__ lw1, const float* __restrict__ lb1,
                      const float* __restrict__ lw2, const float* __restrict__ lb2) {
    extern __shared__ float sm[];
    float* Xs = sm;                   // [64][132]
    float* Ws = sm + 64 * XSS;        // [128][136]
    float* w1s = Ws + 128 * WSS;      // [128]
    float* w2s = w1s + 128;           // [128]
    float* sc1 = w2s + 128;           // [64][2]
    float* sc2 = sc1 + 128;           // [64][2]
    int tile = tbase + blockIdx.x;
    int tid = threadIdx.x;
    int w = tid >> 5, lane = tid & 31;
    int wm = w >> 1, wn = w & 1;
    int mr = wm * 16, cn = wn * 64;
    int g = lane >> 2, tg = lane & 3;

    int s = tile >> 8;
    int lfg = s & 1;
    const float* aw1 = lfg ? lw1 : cw1;
    const float* aw2 = lfg ? lw2 : cw2;
    float ab1 = (lfg ? lb1 : cb1)[0];
    float ab2 = (lfg ? lb2 : cb2)[0];

    const float* X = &d_new[0][0] + (size_t)tile * 64 * Eq;
    for (int q = tid; q < 64 * 32; q += 256) {
        int r = q >> 5, c4 = q & 31;
        cp16(&Xs[r * XSS + c4 * 4], &X[r * Eq + c4 * 4]);
    }
    for (int q = tid; q < 128 * 32; q += 256) {
        int k = q >> 5, c4 = q & 31;
        cp16(&Ws[k * WSS + c4 * 4], &W1[k * Eq + c4 * 4]);
    }
    CP_COMMIT();
    if (tid < 128) { w1s[tid] = aw1[tid]; w2s[tid] = aw2[tid]; }
    CP_WAIT0();
    __syncthreads();

    float acc[8][4];
#pragma unroll
    for (int r = 0; r < 8; r++)
#pragma unroll
        for (int c = 0; c < 4; c++) acc[r][c] = 0.f;
#pragma unroll
    for (int ks = 0; ks < 16; ks++) {
        int k0 = ks * 8;
        unsigned a0 = __float_as_uint(Xs[(mr + g) * XSS + k0 + tg]);
        unsigned a1 = __float_as_uint(Xs[(mr + g + 8) * XSS + k0 + tg]);
        unsigned a2 = __float_as_uint(Xs[(mr + g) * XSS + k0 + tg + 4]);
        unsigned a3 = __float_as_uint(Xs[(mr + g + 8) * XSS + k0 + tg + 4]);
#pragma unroll
        for (int nt = 0; nt < 8; nt++) {
            int n = cn + nt * 8;
            unsigned b0 = __float_as_uint(Ws[(k0 + tg) * WSS + n + g]);
            unsigned b1 = __float_as_uint(Ws[(k0 + tg + 4) * WSS + n + g]);
            asm("mma.sync.aligned.m16n8k8.row.col.f32.tf32.tf32.f32 "
                "{%0,%1,%2,%3}, {%4,%5,%6,%7}, {%8,%9}, {%0,%1,%2,%3};"
                : "+f"(acc[nt][0]), "+f"(acc[nt][1]), "+f"(acc[nt][2]), "+f"(acc[nt][3])
                : "r"(a0), "r"(a1), "r"(a2), "r"(a3), "r"(b0), "r"(b1));
        }
    }
    __syncthreads();

#pragma unroll
    for (int nt = 0; nt < 8; nt++) {
        int n = cn + nt * 8;
        Xs[(mr + g) * XSS + n + 2 * tg]         = fmaxf(acc[nt][0], 0.f);
        Xs[(mr + g) * XSS + n + 2 * tg + 1]     = fmaxf(acc[nt][1], 0.f);
        Xs[(mr + g + 8) * XSS + n + 2 * tg]     = fmaxf(acc[nt][2], 0.f);
        Xs[(mr + g + 8) * XSS + n + 2 * tg + 1] = fmaxf(acc[nt][3], 0.f);
    }
    for (int q = tid; q < 128 * 32; q += 256) {
        int k = q >> 5, c4 = q & 31;
        cp16(&Ws[k * WSS + c4 * 4], &W2[k * Eq + c4 * 4]);
    }
    CP_COMMIT();
    CP_WAIT0();
    __syncthreads();

#pragma unroll
    for (int r = 0; r < 8; r++)
#pragma unroll
        for (int c = 0; c < 4; c++) acc[r][c] = 0.f;
#pragma unroll
    for (int ks = 0; ks < 16; ks++) {
        int k0 = ks * 8;
        unsigned a0 = __float_as_uint(Xs[(mr + g) * XSS + k0 + tg]);
        unsigned a1 = __float_as_uint(Xs[(mr + g + 8) * XSS + k0 + tg]);
        unsigned a2 = __float_as_uint(Xs[(mr + g) * XSS + k0 + tg + 4]);
        unsigned a3 = __float_as_uint(Xs[(mr + g + 8) * XSS + k0 + tg + 4]);
#pragma unroll
        for (int nt = 0; nt < 8; nt++) {
            int n = cn + nt * 8;
            unsigned b0 = __float_as_uint(Ws[(k0 + tg) * WSS + n + g]);
            unsigned b1 = __float_as_uint(Ws[(k0 + tg + 4) * WSS + n + g]);
            asm("mma.sync.aligned.m16n8k8.row.col.f32.tf32.tf32.f32 "
                "{%0,%1,%2,%3}, {%4,%5,%6,%7}, {%8,%9}, {%0,%1,%2,%3};"
                : "+f"(acc[nt][0]), "+f"(acc[nt][1]), "+f"(acc[nt][2]), "+f"(acc[nt][3])
                : "r"(a0), "r"(a1), "r"(a2), "r"(a3), "r"(b0), "r"(b1));
        }
    }

    int side = s >> 1;
    int rbase = tile * 64 - s * BN;

    if (!last) {
        // normal epilogue: emb = tanh(lit+O), next-iteration scores
        float p1[2] = {0.f, 0.f}, p2[2] = {0.f, 0.f};
#pragma unroll
        for (int nt = 0; nt < 8; nt++) {
            int n = cn + nt * 8;
#pragma unroll
            for (int hh = 0; hh < 2; hh++) {
                int rloc = mr + g + hh * 8;
                int row = rbase + rloc;
                float2 lv = *(const float2*)&d_lit[side][(size_t)row * Eq + n + 2 * tg];
                float t0 = tanh_mufu(lv.x + acc[nt][2 * hh + 0]);
                float t1 = tanh_mufu(lv.y + acc[nt][2 * hh + 1]);
                size_t o = ((size_t)tile * 64 + rloc) * Eq + n + 2 * tg;
                *(float2*)&(&d_emb[0][0])[o] = make_float2(t0, t1);
                p1[hh] += t0 * w1s[n + 2 * tg] + t1 * w1s[n + 2 * tg + 1];
                p2[hh] += t0 * w2s[n + 2 * tg] + t1 * w2s[n + 2 * tg + 1];
            }
        }
#pragma unroll
        for (int hh = 0; hh < 2; hh++) {
            p1[hh] += __shfl_xor_sync(0xffffffffu, p1[hh], 1);
            p1[hh] += __shfl_xor_sync(0xffffffffu, p1[hh], 2);
            p2[hh] += __shfl_xor_sync(0xffffffffu, p2[hh], 1);
            p2[hh] += __shfl_xor_sync(0xffffffffu, p2[hh], 2);
            if (tg == 0) {
                int rloc = mr + g + hh * 8;
                sc1[rloc * 2 + wn] = p1[hh];
                sc2[rloc * 2 + wn] = p2[hh];
            }
        }
        __syncthreads();
        if (tid < 64) {
            int bn = rbase + tid;
            d_h1[s][bn] = sc1[tid * 2] + sc1[tid * 2 + 1] + ab1;
            d_h2[s][bn] = sc2[tid * 2] + sc2[tid * 2 + 1] + ab2;
        }
    } else {
        // final iteration: fold column-sums directly into d_mid (no emb store,
        // no scores, no separate colsum kernel)
        float cs0[8], cs1[8];
#pragma unroll
        for (int nt = 0; nt < 8; nt++) { cs0[nt] = 0.f; cs1[nt] = 0.f; }
#pragma unroll
        for (int nt = 0; nt < 8; nt++) {
            int n = cn + nt * 8;
#pragma unroll
            for (int hh = 0; hh < 2; hh++) {
                int rloc = mr + g + hh * 8;
                int row = rbase + rloc;
                float2 lv = *(const float2*)&d_lit[side][(size_t)row * Eq + n + 2 * tg];
                cs0[nt] += tanh_mufu(lv.x + acc[nt][2 * hh + 0]);
                cs1[nt] += tanh_mufu(lv.y + acc[nt][2 * hh + 1]);
            }
        }
        int b = rbase >> 9;                 // batch (tiles never straddle batches)
#pragma unroll
        for (int nt = 0; nt < 8; nt++) {
            // reduce over g (lanes differing in bits 2..4, same tg)
            cs0[nt] += __shfl_xor_sync(0xffffffffu, cs0[nt], 4);
            cs0[nt] += __shfl_xor_sync(0xffffffffu, cs0[nt], 8);
            cs0[nt] += __shfl_xor_sync(0xffffffffu, cs0[nt], 16);
            cs1[nt] += __shfl_xor_sync(0xffffffffu, cs1[nt], 4);
            cs1[nt] += __shfl_xor_sync(0xffffffffu, cs1[nt], 8);
            cs1[nt] += __shfl_xor_sync(0xffffffffu, cs1[nt], 16);
            if (g == 0) {
                int col = cn + nt * 8 + 2 * tg;     // 0..127
                float* dst = &d_mid[side][b * 256 + lfg * 128 + col];
                atomicAdd(dst, cs0[nt]);
                atomicAdd(dst + 1, cs1[nt]);
            }
        }
    }
}

// ---------------- K11: output head + cosine ----------------
__global__ void k_final(const float* __restrict__ Wout, const float* __restrict__ bout,
                        float* __restrict__ out) {
    int b = blockIdx.x;
    int o = threadIdx.x;
    float e[2];
#pragma unroll
    for (int side = 0; side < 2; side++) {
        float a = bout[o];
        const float* mid = d_mid[side] + b * 256;
        for (int k = 0; k < 256; k++) a = fmaf(mid[k], Wout[k * Oq + o], a);
        const float* se = d_sem[side] + b * Eq;
        for (int k = 0; k < 128; k++) a = fmaf(se[k], Wout[(256 + k) * Oq + o], a);
        e[side] = a;
    }
    float p = e[0] * e[1], q0 = e[0] * e[0], q1 = e[1] * e[1];
#pragma unroll
    for (int off = 16; off; off >>= 1) {
        p += __shfl_xor_sync(0xffffffffu, p, off);
        q0 += __shfl_xor_sync(0xffffffffu, q0, off);
        q1 += __shfl_xor_sync(0xffffffffu, q1, off);
    }
    __shared__ float sp[2], s0[2], s1[2];
    if ((o & 31) == 0) { int w = o >> 5; sp[w] = p; s0[w] = q0; s1[w] = q1; }
    __syncthreads();
    if (o == 0) {
        float dot = sp[0] + sp[1];
        float n0 = s0[0] + s0[1];
        float n1 = s1[0] + s1[1];
        out[b] = 0.5f * (1.f + dot * rsqrtf(fmaxf(n0, 1e-12f)) * rsqrtf(fmaxf(n1, 1e-12f)));
    }
}

// ---------------- host launcher ----------------
constexpr int GEMM_SMEM = (Eq * Eq + 64 * Eq) * 4;
constexpr int MLP_SMEM = (64 * XSS + 128 * WSS + 128 + 128 + 128 + 128) * 4;   // 105472
constexpr int AV_SMEM = (2 * 64 * EJS + 512) * 4 + 128 * 16 * 4;               // 79872

extern "C" void kernel_launch(void* const* d_in, const int* in_sizes, int n_in,
                              void* d_out, int out_size) {
    const int* CFG1 = (const int*)d_in[0];
    const int* LFG1 = (const int*)d_in[1];
    const float* LIT1 = (const float*)d_in[2];
    const float* SEM1 = (const float*)d_in[3];
    const int* CFG2 = (const int*)d_in[4];
    const int* LFG2 = (const int*)d_in[5];
    const float* LIT2 = (const float*)d_in[6];
    const float* SEM2 = (const float*)d_in[7];
    const float* Wlit1 = (const float*)d_in[8];
    const float* gk1 = (const float*)d_in[9];
    const float* grk1 = (const float*)d_in[10];
    const float* gb1 = (const float*)d_in[11];
    const float* Wlit2 = (const float*)d_in[12];
    const float* gk2 = (const float*)d_in[13];
    const float* grk2 = (const float*)d_in[14];
    const float* gb2 = (const float*)d_in[15];
    const float* ca1w = (const float*)d_in[16];
    const float* ca1b = (const float*)d_in[17];
    const float* ca2w = (const float*)d_in[18];
    const float* ca2b = (const float*)d_in[19];
    const float* la1w = (const float*)d_in[20];
    const float* la1b = (const float*)d_in[21];
    const float* la2w = (const float*)d_in[22];
    const float* la2b = (const float*)d_in[23];
    const float* mlp1 = (const float*)d_in[24];
    const float* mlp2 = (const float*)d_in[25];
    const float* Wout = (const float*)d_in[26];
    const float* bout = (const float*)d_in[27];
    float* out = (float*)d_out;

    // one-time resources (3 streams — proven to stay inside the memory guard)
    static bool inited = false;
    static cudaStream_t sA, sB, sC;
    static cudaEvent_t evRoot, evP, evB, evA, evC;
    if (!inited) {
        cudaStreamCreateWithFlags(&sA, cudaStreamNonBlocking);
        cudaStreamCreateWithFlags(&sB, cudaStreamNonBlocking);
        cudaStreamCreateWithFlags(&sC, cudaStreamNonBlocking);
        cudaEventCreateWithFlags(&evRoot, cudaEventDisableTiming);
        cudaEventCreateWithFlags(&evP, cudaEventDisableTiming);
        cudaEventCreateWithFlags(&evB, cudaEventDisableTiming);
        cudaEventCreateWithFlags(&evA, cudaEventDisableTiming);
        cudaEventCreateWithFlags(&evC, cudaEventDisableTiming);
        cudaFuncSetAttribute(k_lit, cudaFuncAttributeMaxDynamicSharedMemorySize, GEMM_SMEM);
        cudaFuncSetAttribute(k_xz, cudaFuncAttributeMaxDynamicSharedMemorySize, GEMM_SMEM);
        cudaFuncSetAttribute(k_av, cudaFuncAttributeMaxDynamicSharedMemorySize, AV_SMEM);
        cudaFuncSetAttribute(k_mlp, cudaFuncAttributeMaxDynamicSharedMemorySize, MLP_SMEM);
        inited = true;
    }

    // fork side streams off the capture-origin (legacy) stream
    cudaEventRecord(evRoot, 0);
    cudaStreamWaitEvent(sA, evRoot, 0);
    cudaStreamWaitEvent(sB, evRoot, 0);

    // stream 0: graph bitmask packing (also zeroes d_mid for the atomic colsum)
    k_pack<<<4 * BN * NWORD / 256, 256, 0, 0>>>(CFG1, LFG1, CFG2, LFG2);
    cudaEventRecord(evP, 0);

    // stream sB: lit GEMM -> initial scores (compute-bound, overlaps k_pack)
    k_lit<<<512, 256, GEMM_SMEM, sB>>>(LIT1, LIT2, Wlit1, Wlit2);
    k_scores<<<256, 256, 0, sB>>>(ca1w, ca1b, ca2w, ca2b, la1w, la1b, la2w, la2b);
    cudaEventRecord(evB, sB);

    // stream sA: GRU chain — result only needed by k_final
    k_xz<<<192, 256, GEMM_SMEM, sA>>>(SEM1, SEM2, gk1, gk2, gb1, gb2);
    k_gru<<<64, 384, 0, sA>>>(grk1, grk2, gb1, gb2);
    cudaEventRecord(evA, sA);

    // iteration loop: two independent chains (streams 0..1 | streams 2..3)
    cudaStreamWaitEvent(0, evB, 0);
    cudaStreamWaitEvent(sC, evB, 0);
    cudaStreamWaitEvent(sC, evP, 0);
    for (int it = 0; it < N_ITERS; it++) {
        int last = (it == N_ITERS - 1) ? 1 : 0;
        k_av<<<256, 256, AV_SMEM, 0>>>(0);
        k_mlp<<<512, 256, MLP_SMEM, 0>>>(0, last, mlp1, mlp2,
                                         ca1w, ca1b, ca2w, ca2b,
                                         la1w, la1b, la2w, la2b);
        k_av<<<256, 256, AV_SMEM, sC>>>(2);
        k_mlp<<<512, 256, MLP_SMEM, sC>>>(512, last, mlp1, mlp2,
                                          ca1w, ca1b, ca2w, ca2b,
                                          la1w, la1b, la2w, la2b);
    }
    cudaEventRecord(evC, sC);
    cudaStreamWaitEvent(0, evC, 0);
    cudaStreamWaitEvent(0, evA, 0);
    k_final<<<32, 64, 0, 0>>>(Wout, bout, out);
}